// round 1
// baseline (speedup 1.0000x reference)
#include <cuda_runtime.h>
#include <math.h>

#define B_   8
#define N_   1024
#define D_   384
#define H_   8
#define HD_  48
#define HID_ 1536
#define ROWS (B_ * N_)   // 8192

// ---------------- scratch (device globals; no allocation allowed) ----------
__device__ float g_h  [ROWS * D_];                 // LN output (reused for LN2)
__device__ float g_q  [B_ * H_ * N_ * HD_];
__device__ float g_k  [B_ * H_ * N_ * HD_];
__device__ float g_v  [B_ * H_ * N_ * HD_];
__device__ float g_S  [(size_t)B_ * H_ * N_ * N_]; // mixed scores / probs (in-place)
__device__ float g_o  [ROWS * D_];
__device__ float g_x1 [ROWS * D_];
__device__ float g_act[ROWS * HID_];

// ---------------- LayerNorm: one block per row of 384 ----------------------
__global__ void ln_kernel(const float* __restrict__ x, const float* __restrict__ gw,
                          const float* __restrict__ bw, float* __restrict__ out) {
    int row = blockIdx.x;
    int t   = threadIdx.x;                  // 128 threads
    const float* xr = x + (size_t)row * D_;
    float v0 = xr[t], v1 = xr[t + 128], v2 = xr[t + 256];
    float s  = v0 + v1 + v2;
    float ss = v0 * v0 + v1 * v1 + v2 * v2;
#pragma unroll
    for (int o = 16; o; o >>= 1) {
        s  += __shfl_xor_sync(0xffffffffu, s,  o);
        ss += __shfl_xor_sync(0xffffffffu, ss, o);
    }
    __shared__ float rs[4], rq[4];
    if ((t & 31) == 0) { rs[t >> 5] = s; rq[t >> 5] = ss; }
    __syncthreads();
    s  = rs[0] + rs[1] + rs[2] + rs[3];
    ss = rq[0] + rq[1] + rq[2] + rq[3];
    float mean = s * (1.0f / 384.0f);
    float var  = ss * (1.0f / 384.0f) - mean * mean;
    float rstd = rsqrtf(var + 1e-5f);
    float* orow = out + (size_t)row * D_;
    orow[t]       = (v0 - mean) * rstd * gw[t]       + bw[t];
    orow[t + 128] = (v1 - mean) * rstd * gw[t + 128] + bw[t + 128];
    orow[t + 256] = (v2 - mean) * rstd * gw[t + 256] + bw[t + 256];
}

// ---------------- generic C = A @ B^T GEMM, 128x128x8 tiles ----------------
// MODE 0: qkv scatter (+q scale), MODE 1: bias + exact GELU, MODE 2: bias + resid + layerscale
template <int MODE>
__launch_bounds__(256)
__global__ void gemm_tn(const float* __restrict__ A, const float* __restrict__ Bm,
                        const float* __restrict__ bias, float* __restrict__ C,
                        const float* __restrict__ resid, const float* __restrict__ gamma,
                        float* __restrict__ qo, float* __restrict__ ko, float* __restrict__ vo,
                        int M, int N, int K) {
    __shared__ float As[8][128];
    __shared__ float Bs[8][128];
    int tid = threadIdx.x;
    int tx  = tid & 15, ty = tid >> 4;
    int m0  = blockIdx.y * 128, n0 = blockIdx.x * 128;
    int lr  = tid >> 1;             // 0..127
    int lk  = (tid & 1) * 4;        // 0 or 4
    const float* Ap = A  + (size_t)(m0 + lr) * K + lk;
    const float* Bp = Bm + (size_t)(n0 + lr) * K + lk;

    float acc[8][8];
#pragma unroll
    for (int i = 0; i < 8; i++)
#pragma unroll
        for (int j = 0; j < 8; j++) acc[i][j] = 0.0f;

    for (int k0 = 0; k0 < K; k0 += 8) {
        float4 a4 = *(const float4*)(Ap + k0);
        float4 b4 = *(const float4*)(Bp + k0);
        As[lk + 0][lr] = a4.x; As[lk + 1][lr] = a4.y;
        As[lk + 2][lr] = a4.z; As[lk + 3][lr] = a4.w;
        Bs[lk + 0][lr] = b4.x; Bs[lk + 1][lr] = b4.y;
        Bs[lk + 2][lr] = b4.z; Bs[lk + 3][lr] = b4.w;
        __syncthreads();
#pragma unroll
        for (int k = 0; k < 8; k++) {
            float4 a0 = *(const float4*)&As[k][ty * 4];
            float4 a1 = *(const float4*)&As[k][ty * 4 + 64];
            float4 b0 = *(const float4*)&Bs[k][tx * 4];
            float4 b1 = *(const float4*)&Bs[k][tx * 4 + 64];
            float ar[8] = {a0.x, a0.y, a0.z, a0.w, a1.x, a1.y, a1.z, a1.w};
            float br[8] = {b0.x, b0.y, b0.z, b0.w, b1.x, b1.y, b1.z, b1.w};
#pragma unroll
            for (int i = 0; i < 8; i++)
#pragma unroll
                for (int j = 0; j < 8; j++) acc[i][j] += ar[i] * br[j];
        }
        __syncthreads();
    }

#pragma unroll
    for (int i = 0; i < 8; i++) {
        int row = m0 + ((i < 4) ? (ty * 4 + i) : (64 + ty * 4 + i - 4));
#pragma unroll
        for (int j = 0; j < 8; j++) {
            int col = n0 + ((j < 4) ? (tx * 4 + j) : (64 + tx * 4 + j - 4));
            float v = acc[i][j];
            if (MODE == 0) {
                int t3 = col / D_;
                int r  = col - t3 * D_;
                int hh = r / HD_;
                int dd = r - hh * HD_;
                int bb = row >> 10, ii = row & 1023;
                size_t dst = ((size_t)(bb * H_ + hh) * N_ + ii) * HD_ + dd;
                if (t3 == 0)      qo[dst] = v * 0.14433756729740643f;  // 48^-0.5
                else if (t3 == 1) ko[dst] = v;
                else              vo[dst] = v;
            } else if (MODE == 1) {
                v += bias[col];
                v = 0.5f * v * (1.0f + erff(v * 0.7071067811865475f));
                C[(size_t)row * N + col] = v;
            } else {
                v += bias[col];
                C[(size_t)row * N + col] = resid[(size_t)row * N + col] + gamma[col] * v;
            }
        }
    }
}

// ---------------- fused QK^T + w_l head-mix + b_l ---------------------------
// grid (N/32, N/32, B); block 256; each thread owns a 2x2 patch of all 8 mixed heads
__launch_bounds__(256)
__global__ void score_kernel(const float* __restrict__ q, const float* __restrict__ k,
                             const float* __restrict__ wl, const float* __restrict__ bl,
                             float* __restrict__ S) {
    __shared__ float qs[32][49];
    __shared__ float ks[32][49];
    __shared__ float wls[64], bls[8];
    int tid = threadIdx.x;
    int b   = blockIdx.z;
    int i0  = blockIdx.y * 32, j0 = blockIdx.x * 32;
    if (tid < 64) wls[tid] = wl[tid];
    if (tid < 8)  bls[tid] = bl[tid];
    int tx = tid & 15, ty = tid >> 4;
    int r0 = ty * 2, c0 = tx * 2;

    float macc[8][4];
#pragma unroll
    for (int g = 0; g < 8; g++)
#pragma unroll
        for (int e = 0; e < 4; e++) macc[g][e] = 0.0f;

    for (int h = 0; h < H_; h++) {
        const float* qb = q + ((size_t)(b * H_ + h) * N_ + i0) * HD_;
        const float* kb = k + ((size_t)(b * H_ + h) * N_ + j0) * HD_;
        __syncthreads();
        for (int idx = tid; idx < 32 * 48; idx += 256) {
            int r = idx / 48, c = idx - 48 * r;
            qs[r][c] = qb[(size_t)r * HD_ + c];
            ks[r][c] = kb[(size_t)r * HD_ + c];
        }
        __syncthreads();
        float s00 = 0, s01 = 0, s10 = 0, s11 = 0;
#pragma unroll
        for (int d = 0; d < 48; d++) {
            float qa0 = qs[r0][d],     qa1 = qs[r0 + 1][d];
            float kb0 = ks[c0][d],     kb1 = ks[c0 + 1][d];
            s00 += qa0 * kb0; s01 += qa0 * kb1;
            s10 += qa1 * kb0; s11 += qa1 * kb1;
        }
#pragma unroll
        for (int g = 0; g < 8; g++) {
            float w = wls[g * 8 + h];
            macc[g][0] += w * s00; macc[g][1] += w * s01;
            macc[g][2] += w * s10; macc[g][3] += w * s11;
        }
    }
#pragma unroll
    for (int g = 0; g < 8; g++) {
        float bb = bls[g];
        size_t base = ((size_t)(b * H_ + g) * N_ + i0 + r0) * N_ + j0 + c0;
        S[base]          = macc[g][0] + bb;
        S[base + 1]      = macc[g][1] + bb;
        S[base + N_]     = macc[g][2] + bb;
        S[base + N_ + 1] = macc[g][3] + bb;
    }
}

// ---------------- fused softmax + w_w post-mix + b_w (in place) -------------
// grid 8192 = (b,i); block 256; 8 rows of 1024 in smem
__launch_bounds__(256)
__global__ void softmax_mix_kernel(float* __restrict__ S, const float* __restrict__ ww,
                                   const float* __restrict__ bwv) {
    __shared__ float sp[8][1024];
    __shared__ float wws[64], bws[8];
    int tid = threadIdx.x;
    int bi  = blockIdx.x;
    int b   = bi >> 10, i = bi & 1023;
    if (tid < 64) wws[tid] = ww[tid];
    if (tid < 8)  bws[tid] = bwv[tid];
    for (int g = 0; g < 8; g++) {
        const float* row = S + ((size_t)(b * H_ + g) * N_ + i) * N_;
        for (int j = tid; j < N_; j += 256) sp[g][j] = row[j];
    }
    __syncthreads();
    {   // warp w owns row w
        int g = tid >> 5, l = tid & 31;
        float m = -INFINITY;
        for (int j = l; j < N_; j += 32) m = fmaxf(m, sp[g][j]);
#pragma unroll
        for (int o = 16; o; o >>= 1) m = fmaxf(m, __shfl_xor_sync(0xffffffffu, m, o));
        float sum = 0.0f;
        for (int j = l; j < N_; j += 32) { float e = __expf(sp[g][j] - m); sp[g][j] = e; sum += e; }
#pragma unroll
        for (int o = 16; o; o >>= 1) sum += __shfl_xor_sync(0xffffffffu, sum, o);
        float inv = 1.0f / sum;
        for (int j = l; j < N_; j += 32) sp[g][j] *= inv;
    }
    __syncthreads();
    for (int j = tid; j < N_; j += 256) {
        float ph[8];
#pragma unroll
        for (int h = 0; h < 8; h++) ph[h] = sp[h][j];
#pragma unroll
        for (int g = 0; g < 8; g++) {
            float v = bws[g];
#pragma unroll
            for (int h = 0; h < 8; h++) v += wws[g * 8 + h] * ph[h];
            S[((size_t)(b * H_ + g) * N_ + i) * N_ + j] = v;
        }
    }
}

// ---------------- batched P @ V, writes directly into (B,N,D) ---------------
// grid (16 i-tiles, 64 bh); block 256; each thread 4(i) x 3(d)
__launch_bounds__(256)
__global__ void av_kernel(const float* __restrict__ P, const float* __restrict__ v,
                          float* __restrict__ o) {
    __shared__ float Ps[64][65];
    __shared__ float Vs[64][49];
    int tid = threadIdx.x;
    int i0  = blockIdx.x * 64;
    int bh  = blockIdx.y;
    int b   = bh >> 3, h = bh & 7;
    int tx = tid & 15, ty = tid >> 4;
    float acc[4][3];
#pragma unroll
    for (int a = 0; a < 4; a++)
#pragma unroll
        for (int c = 0; c < 3; c++) acc[a][c] = 0.0f;
    const float* Pb = P + ((size_t)bh * N_ + i0) * N_;
    const float* Vb = v + (size_t)bh * N_ * HD_;
    for (int j0 = 0; j0 < N_; j0 += 64) {
        __syncthreads();
        for (int idx = tid; idx < 64 * 64; idx += 256) {
            int r = idx >> 6, c = idx & 63;
            Ps[r][c] = Pb[(size_t)r * N_ + j0 + c];
        }
        for (int idx = tid; idx < 64 * 48; idx += 256) {
            int r = idx / 48, c = idx - 48 * r;
            Vs[r][c] = Vb[(size_t)(j0 + r) * HD_ + c];
        }
        __syncthreads();
#pragma unroll 8
        for (int j = 0; j < 64; j++) {
            float a0 = Ps[ty * 4 + 0][j], a1 = Ps[ty * 4 + 1][j];
            float a2 = Ps[ty * 4 + 2][j], a3 = Ps[ty * 4 + 3][j];
            float b0 = Vs[j][tx * 3 + 0], b1 = Vs[j][tx * 3 + 1], b2 = Vs[j][tx * 3 + 2];
            acc[0][0] += a0 * b0; acc[0][1] += a0 * b1; acc[0][2] += a0 * b2;
            acc[1][0] += a1 * b0; acc[1][1] += a1 * b1; acc[1][2] += a1 * b2;
            acc[2][0] += a2 * b0; acc[2][1] += a2 * b1; acc[2][2] += a2 * b2;
            acc[3][0] += a3 * b0; acc[3][1] += a3 * b1; acc[3][2] += a3 * b2;
        }
    }
#pragma unroll
    for (int ii = 0; ii < 4; ii++) {
        int row = i0 + ty * 4 + ii;
#pragma unroll
        for (int dd = 0; dd < 3; dd++) {
            int col = h * HD_ + tx * 3 + dd;
            o[((size_t)(b * N_ + row)) * D_ + col] = acc[ii][dd];
        }
    }
}

// ---------------- host launcher --------------------------------------------
extern "C" void kernel_launch(void* const* d_in, const int* in_sizes, int n_in,
                              void* d_out, int out_size) {
    const float* x      = (const float*)d_in[0];
    const float* ln1_g  = (const float*)d_in[1];
    const float* ln1_b  = (const float*)d_in[2];
    const float* w_qkv  = (const float*)d_in[3];
    const float* w_proj = (const float*)d_in[4];
    const float* b_proj = (const float*)d_in[5];
    const float* w_l    = (const float*)d_in[6];
    const float* b_l    = (const float*)d_in[7];
    const float* w_w    = (const float*)d_in[8];
    const float* b_w    = (const float*)d_in[9];
    const float* ln2_g  = (const float*)d_in[10];
    const float* ln2_b  = (const float*)d_in[11];
    const float* w_fc1  = (const float*)d_in[12];
    const float* b_fc1  = (const float*)d_in[13];
    const float* w_fc2  = (const float*)d_in[14];
    const float* b_fc2  = (const float*)d_in[15];
    const float* gamma1 = (const float*)d_in[16];
    const float* gamma2 = (const float*)d_in[17];
    float* out = (float*)d_out;

    float *h, *q, *k, *v, *S, *o, *x1, *act;
    cudaGetSymbolAddress((void**)&h,   g_h);
    cudaGetSymbolAddress((void**)&q,   g_q);
    cudaGetSymbolAddress((void**)&k,   g_k);
    cudaGetSymbolAddress((void**)&v,   g_v);
    cudaGetSymbolAddress((void**)&S,   g_S);
    cudaGetSymbolAddress((void**)&o,   g_o);
    cudaGetSymbolAddress((void**)&x1,  g_x1);
    cudaGetSymbolAddress((void**)&act, g_act);

    // 1. LN1
    ln_kernel<<<ROWS, 128>>>(x, ln1_g, ln1_b, h);
    // 2. QKV GEMM + scatter + q scale
    gemm_tn<0><<<dim3(1152 / 128, ROWS / 128), 256>>>(
        h, w_qkv, nullptr, nullptr, nullptr, nullptr, q, k, v, ROWS, 1152, 384);
    // 3. scores + pre-softmax head mix
    score_kernel<<<dim3(N_ / 32, N_ / 32, B_), 256>>>(q, k, w_l, b_l, S);
    // 4. softmax + post-softmax head mix (in place)
    softmax_mix_kernel<<<ROWS, 256>>>(S, w_w, b_w);
    // 5. P @ V -> (B,N,D)
    av_kernel<<<dim3(N_ / 64, B_ * H_), 256>>>(S, v, o);
    // 6. proj + bias + residual layerscale -> x1
    gemm_tn<2><<<dim3(384 / 128, ROWS / 128), 256>>>(
        o, w_proj, b_proj, x1, x, gamma1, nullptr, nullptr, nullptr, ROWS, 384, 384);
    // 7. LN2
    ln_kernel<<<ROWS, 128>>>(x1, ln2_g, ln2_b, h);
    // 8. FC1 + bias + exact GELU
    gemm_tn<1><<<dim3(1536 / 128, ROWS / 128), 256>>>(
        h, w_fc1, b_fc1, act, nullptr, nullptr, nullptr, nullptr, nullptr, ROWS, 1536, 384);
    // 9. FC2 + bias + residual layerscale -> out
    gemm_tn<2><<<dim3(384 / 128, ROWS / 128), 256>>>(
        act, w_fc2, b_fc2, out, x1, gamma2, nullptr, nullptr, nullptr, ROWS, 384, 1536);
}

// round 4
// speedup vs baseline: 3.7006x; 3.7006x over previous
#include <cuda_runtime.h>
#include <cuda_bf16.h>
#include <cstdint>
#include <math.h>

typedef __nv_bfloat16 bf16;

#define B_   8
#define N_   1024
#define D_   384
#define H_   8
#define HD_  48
#define HID_ 1536
#define ROWS 8192
#define QSCALE 0.14433756729740643f

// ------------------- static scratch (no allocation allowed) -----------------
__device__ bf16  g_hb  [ROWS * D_];
__device__ bf16  g_act [ROWS * HID_];
__device__ bf16  g_q   [B_ * H_ * N_ * HD_];
__device__ bf16  g_k   [B_ * H_ * N_ * HD_];
__device__ bf16  g_vT  [B_ * H_ * 64 * N_];
__device__ bf16  g_S   [(size_t)B_ * H_ * N_ * N_];
__device__ bf16  g_o   [ROWS * D_];
__device__ float g_x1  [ROWS * D_];
__device__ bf16  g_wqkv [3 * D_ * D_];
__device__ bf16  g_wproj[D_ * D_];
__device__ bf16  g_wfc1 [HID_ * D_];
__device__ bf16  g_wfc2 [D_ * HID_];

// ------------------- fp32 -> bf16 convert -----------------------------------
__global__ void cvt_kernel(const float* in, bf16* out, int n4)
{
    int i = blockIdx.x * 256 + threadIdx.x;
    if (i < n4) {
        float4 v = reinterpret_cast<const float4*>(in)[i];
        __nv_bfloat162 p0 = __floats2bfloat162_rn(v.x, v.y);
        __nv_bfloat162 p1 = __floats2bfloat162_rn(v.z, v.w);
        reinterpret_cast<__nv_bfloat162*>(out)[2 * i]     = p0;
        reinterpret_cast<__nv_bfloat162*>(out)[2 * i + 1] = p1;
    }
}

__global__ void zero_kernel(uint32_t* p, int n)
{
    int i = blockIdx.x * 256 + threadIdx.x;
    if (i < n) p[i] = 0u;
}

// ------------------- LayerNorm fp32 -> bf16 ---------------------------------
__global__ void ln_kernel(const float* __restrict__ x, const float* __restrict__ gw,
                          const float* __restrict__ bw, bf16* __restrict__ out)
{
    int row = blockIdx.x;
    int t   = threadIdx.x;
    const float* xr = x + (size_t)row * D_;
    float v0 = xr[t], v1 = xr[t + 128], v2 = xr[t + 256];
    float s  = v0 + v1 + v2;
    float ss = v0 * v0 + v1 * v1 + v2 * v2;
    for (int o = 16; o > 0; o >>= 1) {
        s  += __shfl_xor_sync(0xffffffffu, s,  o);
        ss += __shfl_xor_sync(0xffffffffu, ss, o);
    }
    __shared__ float rs[4];
    __shared__ float rq[4];
    if ((t & 31) == 0) { rs[t >> 5] = s; rq[t >> 5] = ss; }
    __syncthreads();
    s  = rs[0] + rs[1] + rs[2] + rs[3];
    ss = rq[0] + rq[1] + rq[2] + rq[3];
    float mean = s * (1.0f / 384.0f);
    float var  = ss * (1.0f / 384.0f) - mean * mean;
    float rstd = rsqrtf(var + 1e-5f);
    bf16* orow = out + (size_t)row * D_;
    orow[t]       = __float2bfloat16((v0 - mean) * rstd * gw[t]       + bw[t]);
    orow[t + 128] = __float2bfloat16((v1 - mean) * rstd * gw[t + 128] + bw[t + 128]);
    orow[t + 256] = __float2bfloat16((v2 - mean) * rstd * gw[t + 256] + bw[t + 256]);
}

// ------------------- bf16 MMA helper ----------------------------------------
__device__ __forceinline__ void mma16816(float* c, const uint32_t* a, const uint32_t* b)
{
    asm volatile(
        "mma.sync.aligned.m16n8k16.row.col.f32.bf16.bf16.f32 "
        "{%0,%1,%2,%3}, {%4,%5,%6,%7}, {%8,%9}, {%0,%1,%2,%3};\n"
        : "+f"(c[0]), "+f"(c[1]), "+f"(c[2]), "+f"(c[3])
        : "r"(a[0]), "r"(a[1]), "r"(a[2]), "r"(a[3]), "r"(b[0]), "r"(b[1]));
}

// ------------------- tensor-core GEMM  C = A @ B^T --------------------------
// A: M x K row-major (lda); B: N x K row-major (ldb). Tiles 128 x BN, BK = 16.
// MODE 0: qkv scatter (+q scale, v transposed)
// MODE 1: batched scores -> S (b,i,h,j)
// MODE 2: batched AV -> o (b,i,h*48+d), keep col < 48
// MODE 3: bias + exact GELU -> bf16
// MODE 4: bias + residual + layerscale -> fp32
template<int BN, int MODE>
__global__ void __launch_bounds__(256)
gemm_kernel(const bf16* __restrict__ A, const bf16* __restrict__ Bw,
            int M, int N, int K, int lda, int ldb,
            const float* __restrict__ bias, const float* __restrict__ resid,
            const float* __restrict__ gamma, float* __restrict__ fout,
            bf16* __restrict__ bout, bf16* __restrict__ qo,
            bf16* __restrict__ ko, bf16* __restrict__ vo)
{
    constexpr int NT = (BN == 128) ? 8 : 4;
    __shared__ bf16 As[128][24];
    __shared__ bf16 Bs[BN][24];

    const int tid = threadIdx.x;
    const int w = tid >> 5;
    const int l = tid & 31;
    const int g = l >> 2;
    const int t = l & 3;
    const int wm = (w & 3) * 32;
    const int wn = (w >> 2) * (BN / 2);
    const int m0 = blockIdx.y * 128;
    const int n0 = blockIdx.x * BN;
    const int z  = blockIdx.z;
    const int zb = z >> 3;
    const int zh = z & 7;

    const bf16* Ap = A;
    const bf16* Bp = Bw;
    if (MODE == 1) {
        Ap += (size_t)z * N_ * HD_;
        Bp += (size_t)z * N_ * HD_;
    }
    if (MODE == 2) {
        Ap += (size_t)zb * 8388608 + (size_t)zh * 1024;
        Bp += (size_t)z * 64 * 1024;
    }

    const int arow = tid >> 1;
    const int acg  = (tid & 1) * 8;
    const int brow = (BN == 128) ? (tid >> 1) : (tid >> 2);
    const int bcg  = (BN == 128) ? ((tid & 1) * 8) : ((tid & 3) * 4);

    float acc[2][NT][4];
    for (int mi = 0; mi < 2; mi++)
        for (int ni = 0; ni < NT; ni++)
            for (int e = 0; e < 4; e++)
                acc[mi][ni][e] = 0.0f;

    for (int k0 = 0; k0 < K; k0 += 16) {
        uint4 av = *reinterpret_cast<const uint4*>(Ap + (size_t)(m0 + arow) * lda + k0 + acg);
        uint4 bv4;
        uint2 bv2;
        if (BN == 128) {
            bv4 = *reinterpret_cast<const uint4*>(Bp + (size_t)(n0 + brow) * ldb + k0 + bcg);
        } else {
            bv2 = *reinterpret_cast<const uint2*>(Bp + (size_t)(n0 + brow) * ldb + k0 + bcg);
        }
        __syncthreads();
        *reinterpret_cast<uint4*>(&As[arow][acg]) = av;
        if (BN == 128) {
            *reinterpret_cast<uint4*>(&Bs[brow][bcg]) = bv4;
        } else {
            *reinterpret_cast<uint2*>(&Bs[brow][bcg]) = bv2;
        }
        __syncthreads();

        uint32_t af[2][4];
        for (int mi = 0; mi < 2; mi++) {
            int r = wm + mi * 16 + g;
            af[mi][0] = *reinterpret_cast<const uint32_t*>(&As[r][2 * t]);
            af[mi][1] = *reinterpret_cast<const uint32_t*>(&As[r + 8][2 * t]);
            af[mi][2] = *reinterpret_cast<const uint32_t*>(&As[r][2 * t + 8]);
            af[mi][3] = *reinterpret_cast<const uint32_t*>(&As[r + 8][2 * t + 8]);
        }
        uint32_t bf[NT][2];
        for (int ni = 0; ni < NT; ni++) {
            int c = wn + ni * 8 + g;
            bf[ni][0] = *reinterpret_cast<const uint32_t*>(&Bs[c][2 * t]);
            bf[ni][1] = *reinterpret_cast<const uint32_t*>(&Bs[c][2 * t + 8]);
        }
        for (int mi = 0; mi < 2; mi++)
            for (int ni = 0; ni < NT; ni++)
                mma16816(acc[mi][ni], af[mi], bf[ni]);
    }

    for (int mi = 0; mi < 2; mi++) {
        for (int ni = 0; ni < NT; ni++) {
            for (int hh = 0; hh < 2; hh++) {
                int row = m0 + wm + mi * 16 + g + hh * 8;
                int col = n0 + wn + ni * 8 + 2 * t;
                float v0 = acc[mi][ni][hh * 2 + 0];
                float v1 = acc[mi][ni][hh * 2 + 1];
                if (MODE == 0) {
                    int t3 = col / D_;
                    int r  = col - t3 * D_;
                    int hd = r / HD_;
                    int dd = r - hd * HD_;
                    int bb = row >> 10;
                    int ii = row & 1023;
                    size_t qk = ((size_t)(bb * H_ + hd) * N_ + ii) * HD_ + dd;
                    if (t3 == 0) {
                        __nv_bfloat162 p = __floats2bfloat162_rn(v0 * QSCALE, v1 * QSCALE);
                        *reinterpret_cast<__nv_bfloat162*>(&qo[qk]) = p;
                    } else if (t3 == 1) {
                        __nv_bfloat162 p = __floats2bfloat162_rn(v0, v1);
                        *reinterpret_cast<__nv_bfloat162*>(&ko[qk]) = p;
                    } else {
                        size_t vb = ((size_t)(bb * H_ + hd) * 64 + dd) * N_ + ii;
                        vo[vb]      = __float2bfloat16(v0);
                        vo[vb + N_] = __float2bfloat16(v1);
                    }
                } else if (MODE == 1) {
                    size_t idx = ((size_t)(zb * N_ + row) * H_ + zh) * N_ + col;
                    __nv_bfloat162 p = __floats2bfloat162_rn(v0, v1);
                    *reinterpret_cast<__nv_bfloat162*>(&bout[idx]) = p;
                } else if (MODE == 2) {
                    if (col < HD_) {
                        size_t idx = (size_t)(zb * N_ + row) * D_ + zh * HD_ + col;
                        __nv_bfloat162 p = __floats2bfloat162_rn(v0, v1);
                        *reinterpret_cast<__nv_bfloat162*>(&bout[idx]) = p;
                    }
                } else if (MODE == 3) {
                    float a0 = v0 + bias[col];
                    float a1 = v1 + bias[col + 1];
                    a0 = 0.5f * a0 * (1.0f + erff(a0 * 0.7071067811865475f));
                    a1 = 0.5f * a1 * (1.0f + erff(a1 * 0.7071067811865475f));
                    __nv_bfloat162 p = __floats2bfloat162_rn(a0, a1);
                    *reinterpret_cast<__nv_bfloat162*>(&bout[(size_t)row * N + col]) = p;
                } else {
                    float2 rr = *reinterpret_cast<const float2*>(&resid[(size_t)row * N + col]);
                    float2 o2;
                    o2.x = rr.x + gamma[col]     * (v0 + bias[col]);
                    o2.y = rr.y + gamma[col + 1] * (v1 + bias[col + 1]);
                    *reinterpret_cast<float2*>(&fout[(size_t)row * N + col]) = o2;
                }
            }
        }
    }
}

// ------------------- fused premix + softmax + postmix (in place) ------------
__global__ void __launch_bounds__(256)
softmax_kernel(bf16* __restrict__ S, const float* __restrict__ wl,
               const float* __restrict__ bl, const float* __restrict__ ww,
               const float* __restrict__ bw)
{
    __shared__ bf16  sp[8][1024];
    __shared__ float wls[64];
    __shared__ float bls[8];
    __shared__ float wws[64];
    __shared__ float bws[8];
    const int tid = threadIdx.x;
    if (tid < 64) { wls[tid] = wl[tid]; wws[tid] = ww[tid]; }
    if (tid < 8)  { bls[tid] = bl[tid]; bws[tid] = bw[tid]; }
    const int b = blockIdx.x >> 10;
    const int i = blockIdx.x & 1023;
    uint32_t* gbase = reinterpret_cast<uint32_t*>(S + (size_t)(b * N_ + i) * H_ * N_);
    uint32_t* sbase = reinterpret_cast<uint32_t*>(&sp[0][0]);
    for (int idx = tid; idx < 4096; idx += 256) sbase[idx] = gbase[idx];
    __syncthreads();

    for (int jp = tid; jp < 512; jp += 256) {
        float r0[8];
        float r1[8];
        for (int h = 0; h < 8; h++) {
            __nv_bfloat162 p = *reinterpret_cast<__nv_bfloat162*>(&sp[h][2 * jp]);
            r0[h] = __bfloat162float(p.x);
            r1[h] = __bfloat162float(p.y);
        }
        for (int gg = 0; gg < 8; gg++) {
            float m0 = bls[gg];
            float m1 = bls[gg];
            for (int h = 0; h < 8; h++) {
                m0 += wls[gg * 8 + h] * r0[h];
                m1 += wls[gg * 8 + h] * r1[h];
            }
            *reinterpret_cast<__nv_bfloat162*>(&sp[gg][2 * jp]) = __floats2bfloat162_rn(m0, m1);
        }
    }
    __syncthreads();

    {
        const int gg = tid >> 5;
        const int l  = tid & 31;
        float mx = -1e30f;
        for (int j = l; j < N_; j += 32) mx = fmaxf(mx, __bfloat162float(sp[gg][j]));
        for (int o = 16; o > 0; o >>= 1) mx = fmaxf(mx, __shfl_xor_sync(0xffffffffu, mx, o));
        float sum = 0.0f;
        for (int j = l; j < N_; j += 32) {
            float e = __expf(__bfloat162float(sp[gg][j]) - mx);
            sum += e;
            sp[gg][j] = __float2bfloat16(e);
        }
        for (int o = 16; o > 0; o >>= 1) sum += __shfl_xor_sync(0xffffffffu, sum, o);
        float inv = 1.0f / sum;
        for (int j = l; j < N_; j += 32)
            sp[gg][j] = __float2bfloat16(__bfloat162float(sp[gg][j]) * inv);
    }
    __syncthreads();

    for (int jp = tid; jp < 512; jp += 256) {
        float r0[8];
        float r1[8];
        for (int h = 0; h < 8; h++) {
            __nv_bfloat162 p = *reinterpret_cast<__nv_bfloat162*>(&sp[h][2 * jp]);
            r0[h] = __bfloat162float(p.x);
            r1[h] = __bfloat162float(p.y);
        }
        for (int gg = 0; gg < 8; gg++) {
            float m0 = bws[gg];
            float m1 = bws[gg];
            for (int h = 0; h < 8; h++) {
                m0 += wws[gg * 8 + h] * r0[h];
                m1 += wws[gg * 8 + h] * r1[h];
            }
            reinterpret_cast<__nv_bfloat162*>(gbase)[gg * 512 + jp] =
                __floats2bfloat162_rn(m0, m1);
        }
    }
}

// ------------------- host launcher ------------------------------------------
extern "C" void kernel_launch(void* const* d_in, const int* in_sizes, int n_in,
                              void* d_out, int out_size)
{
    (void)in_sizes; (void)n_in; (void)out_size;
    const float* x      = (const float*)d_in[0];
    const float* ln1_g  = (const float*)d_in[1];
    const float* ln1_b  = (const float*)d_in[2];
    const float* w_qkv  = (const float*)d_in[3];
    const float* w_proj = (const float*)d_in[4];
    const float* b_proj = (const float*)d_in[5];
    const float* w_l    = (const float*)d_in[6];
    const float* b_l    = (const float*)d_in[7];
    const float* w_w    = (const float*)d_in[8];
    const float* b_w    = (const float*)d_in[9];
    const float* ln2_g  = (const float*)d_in[10];
    const float* ln2_b  = (const float*)d_in[11];
    const float* w_fc1  = (const float*)d_in[12];
    const float* b_fc1  = (const float*)d_in[13];
    const float* w_fc2  = (const float*)d_in[14];
    const float* b_fc2  = (const float*)d_in[15];
    const float* gamma1 = (const float*)d_in[16];
    const float* gamma2 = (const float*)d_in[17];
    float* out = (float*)d_out;

    bf16 *hb, *act, *qb, *kb, *vT, *S, *o, *wqkvb, *wprojb, *wfc1b, *wfc2b;
    float* x1;
    cudaGetSymbolAddress((void**)&hb,     g_hb);
    cudaGetSymbolAddress((void**)&act,    g_act);
    cudaGetSymbolAddress((void**)&qb,     g_q);
    cudaGetSymbolAddress((void**)&kb,     g_k);
    cudaGetSymbolAddress((void**)&vT,     g_vT);
    cudaGetSymbolAddress((void**)&S,      g_S);
    cudaGetSymbolAddress((void**)&o,      g_o);
    cudaGetSymbolAddress((void**)&x1,     g_x1);
    cudaGetSymbolAddress((void**)&wqkvb,  g_wqkv);
    cudaGetSymbolAddress((void**)&wprojb, g_wproj);
    cudaGetSymbolAddress((void**)&wfc1b,  g_wfc1);
    cudaGetSymbolAddress((void**)&wfc2b,  g_wfc2);

    const int n1 = 3 * D_ * D_ / 4;
    const int n2 = D_ * D_ / 4;
    const int n3 = HID_ * D_ / 4;
    const int nz = B_ * H_ * 64 * N_ / 2;

    cvt_kernel<<<(n1 + 255) / 256, 256>>>(w_qkv,  wqkvb,  n1);
    cvt_kernel<<<(n2 + 255) / 256, 256>>>(w_proj, wprojb, n2);
    cvt_kernel<<<(n3 + 255) / 256, 256>>>(w_fc1,  wfc1b,  n3);
    cvt_kernel<<<(n3 + 255) / 256, 256>>>(w_fc2,  wfc2b,  n3);
    zero_kernel<<<(nz + 255) / 256, 256>>>((uint32_t*)vT, nz);

    ln_kernel<<<ROWS, 128>>>(x, ln1_g, ln1_b, hb);

    gemm_kernel<128, 0><<<dim3(9, 64, 1), 256>>>(
        hb, wqkvb, ROWS, 1152, 384, 384, 384,
        nullptr, nullptr, nullptr, nullptr, nullptr, qb, kb, vT);

    gemm_kernel<128, 1><<<dim3(8, 8, 64), 256>>>(
        qb, kb, N_, N_, HD_, HD_, HD_,
        nullptr, nullptr, nullptr, nullptr, S, nullptr, nullptr, nullptr);

    softmax_kernel<<<ROWS, 256>>>(S, w_l, b_l, w_w, b_w);

    gemm_kernel<64, 2><<<dim3(1, 8, 64), 256>>>(
        S, vT, N_, 64, N_, 8 * N_, N_,
        nullptr, nullptr, nullptr, nullptr, o, nullptr, nullptr, nullptr);

    gemm_kernel<128, 4><<<dim3(3, 64, 1), 256>>>(
        o, wprojb, ROWS, D_, D_, D_, D_,
        b_proj, x, gamma1, x1, nullptr, nullptr, nullptr, nullptr);

    ln_kernel<<<ROWS, 128>>>(x1, ln2_g, ln2_b, hb);

    gemm_kernel<128, 3><<<dim3(12, 64, 1), 256>>>(
        hb, wfc1b, ROWS, HID_, D_, D_, D_,
        b_fc1, nullptr, nullptr, nullptr, act, nullptr, nullptr, nullptr);

    gemm_kernel<128, 4><<<dim3(3, 64, 1), 256>>>(
        act, wfc2b, ROWS, D_, HID_, HID_, HID_,
        b_fc2, x1, gamma2, out, nullptr, nullptr, nullptr, nullptr);
}

// round 7
// speedup vs baseline: 4.0113x; 1.0840x over previous
#include <cuda_runtime.h>
#include <cuda_bf16.h>
#include <cstdint>
#include <math.h>

typedef __nv_bfloat16 bf16;

#define B_   8
#define N_   1024
#define D_   384
#define H_   8
#define HD_  48
#define HID_ 1536
#define ROWS 8192
#define QSCALE 0.14433756729740643f

// ------------------- static scratch (no allocation allowed) -----------------
__device__ bf16  g_hb  [ROWS * D_];
__device__ bf16  g_act [ROWS * HID_];
__device__ bf16  g_q   [B_ * H_ * N_ * HD_];
__device__ bf16  g_k   [B_ * H_ * N_ * HD_];
__device__ bf16  g_vT  [B_ * H_ * 64 * N_];   // zero-init; pad rows 48..63 never written
__device__ bf16  g_S   [(size_t)B_ * H_ * N_ * N_];
__device__ bf16  g_o   [ROWS * D_];
__device__ float g_x1  [ROWS * D_];
__device__ bf16  g_wqkv [3 * D_ * D_];
__device__ bf16  g_wproj[D_ * D_];
__device__ bf16  g_wfc1 [HID_ * D_];
__device__ bf16  g_wfc2 [D_ * HID_];

// ------------------- fused fp32 -> bf16 convert for all 4 weights -----------
__global__ void cvt_all_kernel(const float* w0, bf16* o0, const float* w1, bf16* o1,
                               const float* w2, bf16* o2, const float* w3, bf16* o3)
{
    int i = blockIdx.x * 256 + threadIdx.x;            // float4 index
    const float* src;
    bf16* dst;
    int base;
    if (i < 110592)       { src = w0; dst = o0; base = i; }
    else if (i < 147456)  { src = w1; dst = o1; base = i - 110592; }
    else if (i < 294912)  { src = w2; dst = o2; base = i - 147456; }
    else if (i < 442368)  { src = w3; dst = o3; base = i - 294912; }
    else return;
    float4 v = reinterpret_cast<const float4*>(src)[base];
    reinterpret_cast<__nv_bfloat162*>(dst)[2 * base]     = __floats2bfloat162_rn(v.x, v.y);
    reinterpret_cast<__nv_bfloat162*>(dst)[2 * base + 1] = __floats2bfloat162_rn(v.z, v.w);
}

// ------------------- LayerNorm fp32 -> bf16 ---------------------------------
__global__ void ln_kernel(const float* __restrict__ x, const float* __restrict__ gw,
                          const float* __restrict__ bw, bf16* __restrict__ out)
{
    int row = blockIdx.x;
    int t   = threadIdx.x;
    const float* xr = x + (size_t)row * D_;
    float v0 = xr[t], v1 = xr[t + 128], v2 = xr[t + 256];
    float s  = v0 + v1 + v2;
    float ss = v0 * v0 + v1 * v1 + v2 * v2;
    for (int o = 16; o > 0; o >>= 1) {
        s  += __shfl_xor_sync(0xffffffffu, s,  o);
        ss += __shfl_xor_sync(0xffffffffu, ss, o);
    }
    __shared__ float rs[4];
    __shared__ float rq[4];
    if ((t & 31) == 0) { rs[t >> 5] = s; rq[t >> 5] = ss; }
    __syncthreads();
    s  = rs[0] + rs[1] + rs[2] + rs[3];
    ss = rq[0] + rq[1] + rq[2] + rq[3];
    float mean = s * (1.0f / 384.0f);
    float var  = ss * (1.0f / 384.0f) - mean * mean;
    float rstd = rsqrtf(var + 1e-5f);
    bf16* orow = out + (size_t)row * D_;
    orow[t]       = __float2bfloat16((v0 - mean) * rstd * gw[t]       + bw[t]);
    orow[t + 128] = __float2bfloat16((v1 - mean) * rstd * gw[t + 128] + bw[t + 128]);
    orow[t + 256] = __float2bfloat16((v2 - mean) * rstd * gw[t + 256] + bw[t + 256]);
}

// ------------------- PTX helpers --------------------------------------------
__device__ __forceinline__ void mma16816(float* c, const uint32_t* a, const uint32_t* b)
{
    asm volatile(
        "mma.sync.aligned.m16n8k16.row.col.f32.bf16.bf16.f32 "
        "{%0,%1,%2,%3}, {%4,%5,%6,%7}, {%8,%9}, {%0,%1,%2,%3};\n"
        : "+f"(c[0]), "+f"(c[1]), "+f"(c[2]), "+f"(c[3])
        : "r"(a[0]), "r"(a[1]), "r"(a[2]), "r"(a[3]), "r"(b[0]), "r"(b[1]));
}

__device__ __forceinline__ void cp_async16(uint32_t dst, const void* src)
{
    asm volatile("cp.async.cg.shared.global [%0], [%1], 16;\n" :: "r"(dst), "l"(src));
}
__device__ __forceinline__ void cp_commit()
{
    asm volatile("cp.async.commit_group;\n");
}
__device__ __forceinline__ void cp_wait0()
{
    asm volatile("cp.async.wait_group 0;\n" ::: "memory");
}

// ------------------- tensor-core GEMM  C = A @ B^T --------------------------
// A: M x K row-major (lda); B: N x K row-major (ldb). Tile BM x BN, BK = 16,
// 2-stage cp.async pipeline, 256 threads (8 warps).
// MODE 0: qkv scatter (+q scale, v transposed)
// MODE 1: batched scores -> S (b,i,h,j)
// MODE 2: batched AV -> o (b,i,h*48+d), keep col < 48
// MODE 3: bias + exact GELU -> bf16
// MODE 4: bias + residual + layerscale -> fp32
template<int BM, int BN, int MODE>
__global__ void __launch_bounds__(256)
gemm_kernel(const bf16* __restrict__ A, const bf16* __restrict__ Bw,
            int M, int N, int K, int lda, int ldb,
            const float* __restrict__ bias, const float* __restrict__ resid,
            const float* __restrict__ gamma, float* __restrict__ fout,
            bf16* __restrict__ bout, bf16* __restrict__ qo,
            bf16* __restrict__ ko, bf16* __restrict__ vo)
{
    constexpr int WM_CNT = BM / 32;                 // warps along M (4 or 2)
    constexpr int WN_TILE = BN * WM_CNT / 8;        // warp tile width along N
    constexpr int NT = WN_TILE / 8;                 // n-fragments per warp

    __shared__ bf16 As[2][BM][24];
    __shared__ bf16 Bs[2][BN][24];

    const int tid = threadIdx.x;
    const int w = tid >> 5;
    const int l = tid & 31;
    const int g = l >> 2;
    const int t = l & 3;
    const int wm = (w % WM_CNT) * 32;
    const int wn = (w / WM_CNT) * WN_TILE;
    const int m0 = blockIdx.y * BM;
    const int n0 = blockIdx.x * BN;
    const int z  = blockIdx.z;
    const int zb = z >> 3;
    const int zh = z & 7;

    const bf16* Ap = A;
    const bf16* Bp = Bw;
    if (MODE == 1) {
        Ap += (size_t)z * N_ * HD_;
        Bp += (size_t)z * N_ * HD_;
    }
    if (MODE == 2) {
        Ap += (size_t)zb * 8388608 + (size_t)zh * 1024;
        Bp += (size_t)z * 64 * 1024;
    }

    const int arow = tid >> 1;
    const int acg  = (tid & 1) * 8;
    const int brow = tid >> 1;
    const int bcg  = (tid & 1) * 8;
    const bool doA = (tid < BM * 2);
    const bool doB = (tid < BN * 2);

    const bf16* aSrc = Ap + (size_t)(m0 + arow) * lda + acg;
    const bf16* bSrc = Bp + (size_t)(n0 + brow) * ldb + bcg;
    uint32_t aDst0 = (uint32_t)__cvta_generic_to_shared(&As[0][arow & (BM - 1)][acg]);
    uint32_t aDst1 = (uint32_t)__cvta_generic_to_shared(&As[1][arow & (BM - 1)][acg]);
    uint32_t bDst0 = (uint32_t)__cvta_generic_to_shared(&Bs[0][brow & (BN - 1)][bcg]);
    uint32_t bDst1 = (uint32_t)__cvta_generic_to_shared(&Bs[1][brow & (BN - 1)][bcg]);

    float acc[2][NT][4];
    for (int mi = 0; mi < 2; mi++)
        for (int ni = 0; ni < NT; ni++)
            for (int e = 0; e < 4; e++)
                acc[mi][ni][e] = 0.0f;

    // prologue: stage 0
    if (doA) cp_async16(aDst0, aSrc);
    if (doB) cp_async16(bDst0, bSrc);
    cp_commit();

    const int niter = K >> 4;
    for (int it = 0; it < niter; it++) {
        cp_wait0();
        __syncthreads();
        if (it + 1 < niter) {
            int kn = (it + 1) << 4;
            uint32_t ad = ((it + 1) & 1) ? aDst1 : aDst0;
            uint32_t bd = ((it + 1) & 1) ? bDst1 : bDst0;
            if (doA) cp_async16(ad, aSrc + kn);
            if (doB) cp_async16(bd, bSrc + kn);
            cp_commit();
        }
        const int buf = it & 1;

        uint32_t af[2][4];
        for (int mi = 0; mi < 2; mi++) {
            int r = wm + mi * 16 + g;
            af[mi][0] = *reinterpret_cast<const uint32_t*>(&As[buf][r][2 * t]);
            af[mi][1] = *reinterpret_cast<const uint32_t*>(&As[buf][r + 8][2 * t]);
            af[mi][2] = *reinterpret_cast<const uint32_t*>(&As[buf][r][2 * t + 8]);
            af[mi][3] = *reinterpret_cast<const uint32_t*>(&As[buf][r + 8][2 * t + 8]);
        }
        uint32_t bfm[NT][2];
        for (int ni = 0; ni < NT; ni++) {
            int c = wn + ni * 8 + g;
            bfm[ni][0] = *reinterpret_cast<const uint32_t*>(&Bs[buf][c][2 * t]);
            bfm[ni][1] = *reinterpret_cast<const uint32_t*>(&Bs[buf][c][2 * t + 8]);
        }
        for (int mi = 0; mi < 2; mi++)
            for (int ni = 0; ni < NT; ni++)
                mma16816(acc[mi][ni], af[mi], bfm[ni]);
    }

    // ------------------------------ epilogue --------------------------------
    for (int mi = 0; mi < 2; mi++) {
        for (int ni = 0; ni < NT; ni++) {
            for (int hh = 0; hh < 2; hh++) {
                int row = m0 + wm + mi * 16 + g + hh * 8;
                int col = n0 + wn + ni * 8 + 2 * t;
                float v0 = acc[mi][ni][hh * 2 + 0];
                float v1 = acc[mi][ni][hh * 2 + 1];
                if (MODE == 0) {
                    int t3 = col / D_;
                    int r  = col - t3 * D_;
                    int hd = r / HD_;
                    int dd = r - hd * HD_;
                    int bb = row >> 10;
                    int ii = row & 1023;
                    size_t qk = ((size_t)(bb * H_ + hd) * N_ + ii) * HD_ + dd;
                    if (t3 == 0) {
                        __nv_bfloat162 p = __floats2bfloat162_rn(v0 * QSCALE, v1 * QSCALE);
                        *reinterpret_cast<__nv_bfloat162*>(&qo[qk]) = p;
                    } else if (t3 == 1) {
                        __nv_bfloat162 p = __floats2bfloat162_rn(v0, v1);
                        *reinterpret_cast<__nv_bfloat162*>(&ko[qk]) = p;
                    } else {
                        size_t vb = ((size_t)(bb * H_ + hd) * 64 + dd) * N_ + ii;
                        vo[vb]      = __float2bfloat16(v0);
                        vo[vb + N_] = __float2bfloat16(v1);
                    }
                } else if (MODE == 1) {
                    size_t idx = ((size_t)(zb * N_ + row) * H_ + zh) * N_ + col;
                    __nv_bfloat162 p = __floats2bfloat162_rn(v0, v1);
                    *reinterpret_cast<__nv_bfloat162*>(&bout[idx]) = p;
                } else if (MODE == 2) {
                    if (col < HD_) {
                        size_t idx = (size_t)(zb * N_ + row) * D_ + zh * HD_ + col;
                        __nv_bfloat162 p = __floats2bfloat162_rn(v0, v1);
                        *reinterpret_cast<__nv_bfloat162*>(&bout[idx]) = p;
                    }
                } else if (MODE == 3) {
                    float a0 = v0 + bias[col];
                    float a1 = v1 + bias[col + 1];
                    a0 = 0.5f * a0 * (1.0f + erff(a0 * 0.7071067811865475f));
                    a1 = 0.5f * a1 * (1.0f + erff(a1 * 0.7071067811865475f));
                    __nv_bfloat162 p = __floats2bfloat162_rn(a0, a1);
                    *reinterpret_cast<__nv_bfloat162*>(&bout[(size_t)row * N + col]) = p;
                } else {
                    float2 rr = *reinterpret_cast<const float2*>(&resid[(size_t)row * N + col]);
                    float2 o2;
                    o2.x = rr.x + gamma[col]     * (v0 + bias[col]);
                    o2.y = rr.y + gamma[col + 1] * (v1 + bias[col + 1]);
                    *reinterpret_cast<float2*>(&fout[(size_t)row * N + col]) = o2;
                }
            }
        }
    }
}

// ------------------- fused premix + softmax + postmix (in place) ------------
__global__ void __launch_bounds__(256)
softmax_kernel(bf16* __restrict__ S, const float* __restrict__ wl,
               const float* __restrict__ bl, const float* __restrict__ ww,
               const float* __restrict__ bw)
{
    __shared__ bf16  sp[8][1024];
    __shared__ float wls[64];
    __shared__ float bls[8];
    __shared__ float wws[64];
    __shared__ float bws[8];
    const int tid = threadIdx.x;
    if (tid < 64) { wls[tid] = wl[tid]; wws[tid] = ww[tid]; }
    if (tid < 8)  { bls[tid] = bl[tid]; bws[tid] = bw[tid]; }
    const int b = blockIdx.x >> 10;
    const int i = blockIdx.x & 1023;
    uint32_t* gbase = reinterpret_cast<uint32_t*>(S + (size_t)(b * N_ + i) * H_ * N_);
    uint32_t* sbase = reinterpret_cast<uint32_t*>(&sp[0][0]);
    for (int idx = tid; idx < 4096; idx += 256) sbase[idx] = gbase[idx];
    __syncthreads();

    for (int jp = tid; jp < 512; jp += 256) {
        float r0[8];
        float r1[8];
        for (int h = 0; h < 8; h++) {
            __nv_bfloat162 p = *reinterpret_cast<__nv_bfloat162*>(&sp[h][2 * jp]);
            r0[h] = __bfloat162float(p.x);
            r1[h] = __bfloat162float(p.y);
        }
        for (int gg = 0; gg < 8; gg++) {
            float m0 = bls[gg];
            float m1 = bls[gg];
            for (int h = 0; h < 8; h++) {
                m0 += wls[gg * 8 + h] * r0[h];
                m1 += wls[gg * 8 + h] * r1[h];
            }
            *reinterpret_cast<__nv_bfloat162*>(&sp[gg][2 * jp]) = __floats2bfloat162_rn(m0, m1);
        }
    }
    __syncthreads();

    {
        const int gg = tid >> 5;
        const int l  = tid & 31;
        float mx = -1e30f;
        for (int j = l; j < N_; j += 32) mx = fmaxf(mx, __bfloat162float(sp[gg][j]));
        for (int o = 16; o > 0; o >>= 1) mx = fmaxf(mx, __shfl_xor_sync(0xffffffffu, mx, o));
        float sum = 0.0f;
        for (int j = l; j < N_; j += 32) {
            float e = __expf(__bfloat162float(sp[gg][j]) - mx);
            sum += e;
            sp[gg][j] = __float2bfloat16(e);
        }
        for (int o = 16; o > 0; o >>= 1) sum += __shfl_xor_sync(0xffffffffu, sum, o);
        float inv = 1.0f / sum;
        for (int j = l; j < N_; j += 32)
            sp[gg][j] = __float2bfloat16(__bfloat162float(sp[gg][j]) * inv);
    }
    __syncthreads();

    for (int jp = tid; jp < 512; jp += 256) {
        float r0[8];
        float r1[8];
        for (int h = 0; h < 8; h++) {
            __nv_bfloat162 p = *reinterpret_cast<__nv_bfloat162*>(&sp[h][2 * jp]);
            r0[h] = __bfloat162float(p.x);
            r1[h] = __bfloat162float(p.y);
        }
        for (int gg = 0; gg < 8; gg++) {
            float m0 = bws[gg];
            float m1 = bws[gg];
            for (int h = 0; h < 8; h++) {
                m0 += wws[gg * 8 + h] * r0[h];
                m1 += wws[gg * 8 + h] * r1[h];
            }
            reinterpret_cast<__nv_bfloat162*>(gbase)[gg * 512 + jp] =
                __floats2bfloat162_rn(m0, m1);
        }
    }
}

// ------------------- host launcher ------------------------------------------
extern "C" void kernel_launch(void* const* d_in, const int* in_sizes, int n_in,
                              void* d_out, int out_size)
{
    (void)in_sizes; (void)n_in; (void)out_size;
    const float* x      = (const float*)d_in[0];
    const float* ln1_g  = (const float*)d_in[1];
    const float* ln1_b  = (const float*)d_in[2];
    const float* w_qkv  = (const float*)d_in[3];
    const float* w_proj = (const float*)d_in[4];
    const float* b_proj = (const float*)d_in[5];
    const float* w_l    = (const float*)d_in[6];
    const float* b_l    = (const float*)d_in[7];
    const float* w_w    = (const float*)d_in[8];
    const float* b_w    = (const float*)d_in[9];
    const float* ln2_g  = (const float*)d_in[10];
    const float* ln2_b  = (const float*)d_in[11];
    const float* w_fc1  = (const float*)d_in[12];
    const float* b_fc1  = (const float*)d_in[13];
    const float* w_fc2  = (const float*)d_in[14];
    const float* b_fc2  = (const float*)d_in[15];
    const float* gamma1 = (const float*)d_in[16];
    const float* gamma2 = (const float*)d_in[17];
    float* out = (float*)d_out;

    bf16 *hb, *act, *qb, *kb, *vT, *S, *o, *wqkvb, *wprojb, *wfc1b, *wfc2b;
    float* x1;
    cudaGetSymbolAddress((void**)&hb,     g_hb);
    cudaGetSymbolAddress((void**)&act,    g_act);
    cudaGetSymbolAddress((void**)&qb,     g_q);
    cudaGetSymbolAddress((void**)&kb,     g_k);
    cudaGetSymbolAddress((void**)&vT,     g_vT);
    cudaGetSymbolAddress((void**)&S,      g_S);
    cudaGetSymbolAddress((void**)&o,      g_o);
    cudaGetSymbolAddress((void**)&x1,     g_x1);
    cudaGetSymbolAddress((void**)&wqkvb,  g_wqkv);
    cudaGetSymbolAddress((void**)&wprojb, g_wproj);
    cudaGetSymbolAddress((void**)&wfc1b,  g_wfc1);
    cudaGetSymbolAddress((void**)&wfc2b,  g_wfc2);

    // all 4 weight conversions in one launch (442368 float4s)
    cvt_all_kernel<<<1728, 256>>>(w_qkv, wqkvb, w_proj, wprojb,
                                  w_fc1, wfc1b, w_fc2, wfc2b);

    ln_kernel<<<ROWS, 128>>>(x, ln1_g, ln1_b, hb);

    gemm_kernel<128, 128, 0><<<dim3(9, 64, 1), 256>>>(
        hb, wqkvb, ROWS, 1152, 384, 384, 384,
        nullptr, nullptr, nullptr, nullptr, nullptr, qb, kb, vT);

    gemm_kernel<128, 128, 1><<<dim3(8, 8, 64), 256>>>(
        qb, kb, N_, N_, HD_, HD_, HD_,
        nullptr, nullptr, nullptr, nullptr, S, nullptr, nullptr, nullptr);

    softmax_kernel<<<ROWS, 256>>>(S, w_l, b_l, w_w, b_w);

    gemm_kernel<128, 64, 2><<<dim3(1, 8, 64), 256>>>(
        S, vT, N_, 64, N_, 8 * N_, N_,
        nullptr, nullptr, nullptr, nullptr, o, nullptr, nullptr, nullptr);

    gemm_kernel<64, 128, 4><<<dim3(3, 128, 1), 256>>>(
        o, wprojb, ROWS, D_, D_, D_, D_,
        b_proj, x, gamma1, x1, nullptr, nullptr, nullptr, nullptr);

    ln_kernel<<<ROWS, 128>>>(x1, ln2_g, ln2_b, hb);

    gemm_kernel<128, 128, 3><<<dim3(12, 64, 1), 256>>>(
        hb, wfc1b, ROWS, HID_, D_, D_, D_,
        b_fc1, nullptr, nullptr, nullptr, act, nullptr, nullptr, nullptr);

    gemm_kernel<64, 128, 4><<<dim3(3, 128, 1), 256>>>(
        act, wfc2b, ROWS, D_, HID_, HID_, HID_,
        b_fc2, x1, gamma2, out, nullptr, nullptr, nullptr, nullptr);
}

// round 8
// speedup vs baseline: 4.1361x; 1.0311x over previous
#include <cuda_runtime.h>
#include <cuda_bf16.h>
#include <cstdint>
#include <math.h>

typedef __nv_bfloat16 bf16;

#define B_   8
#define N_   1024
#define D_   384
#define H_   8
#define HD_  48
#define HID_ 1536
#define ROWS 8192
#define QSCALE 0.14433756729740643f

// ------------------- static scratch (no allocation allowed) -----------------
__device__ bf16  g_hb  [ROWS * D_];
__device__ bf16  g_act [ROWS * HID_];
__device__ bf16  g_q   [B_ * H_ * N_ * HD_];
__device__ bf16  g_k   [B_ * H_ * N_ * HD_];
__device__ bf16  g_vT  [B_ * H_ * 64 * N_];   // zero-init; pad rows 48..63 never written
__device__ bf16  g_S   [(size_t)B_ * H_ * N_ * N_];
__device__ bf16  g_o   [ROWS * D_];
__device__ float g_x1  [ROWS * D_];
__device__ bf16  g_wqkv [3 * D_ * D_];
__device__ bf16  g_wproj[D_ * D_];
__device__ bf16  g_wfc1 [HID_ * D_];
__device__ bf16  g_wfc2 [D_ * HID_];

// ------------------- fused fp32 -> bf16 convert for all 4 weights -----------
__global__ void cvt_all_kernel(const float* w0, bf16* o0, const float* w1, bf16* o1,
                               const float* w2, bf16* o2, const float* w3, bf16* o3)
{
    int i = blockIdx.x * 256 + threadIdx.x;            // float4 index
    const float* src;
    bf16* dst;
    int base;
    if (i < 110592)       { src = w0; dst = o0; base = i; }
    else if (i < 147456)  { src = w1; dst = o1; base = i - 110592; }
    else if (i < 294912)  { src = w2; dst = o2; base = i - 147456; }
    else if (i < 442368)  { src = w3; dst = o3; base = i - 294912; }
    else return;
    float4 v = reinterpret_cast<const float4*>(src)[base];
    reinterpret_cast<__nv_bfloat162*>(dst)[2 * base]     = __floats2bfloat162_rn(v.x, v.y);
    reinterpret_cast<__nv_bfloat162*>(dst)[2 * base + 1] = __floats2bfloat162_rn(v.z, v.w);
}

// ------------------- LayerNorm fp32 -> bf16 ---------------------------------
__global__ void ln_kernel(const float* __restrict__ x, const float* __restrict__ gw,
                          const float* __restrict__ bw, bf16* __restrict__ out)
{
    int row = blockIdx.x;
    int t   = threadIdx.x;
    const float* xr = x + (size_t)row * D_;
    float v0 = xr[t], v1 = xr[t + 128], v2 = xr[t + 256];
    float s  = v0 + v1 + v2;
    float ss = v0 * v0 + v1 * v1 + v2 * v2;
    for (int o = 16; o > 0; o >>= 1) {
        s  += __shfl_xor_sync(0xffffffffu, s,  o);
        ss += __shfl_xor_sync(0xffffffffu, ss, o);
    }
    __shared__ float rs[4];
    __shared__ float rq[4];
    if ((t & 31) == 0) { rs[t >> 5] = s; rq[t >> 5] = ss; }
    __syncthreads();
    s  = rs[0] + rs[1] + rs[2] + rs[3];
    ss = rq[0] + rq[1] + rq[2] + rq[3];
    float mean = s * (1.0f / 384.0f);
    float var  = ss * (1.0f / 384.0f) - mean * mean;
    float rstd = rsqrtf(var + 1e-5f);
    bf16* orow = out + (size_t)row * D_;
    orow[t]       = __float2bfloat16((v0 - mean) * rstd * gw[t]       + bw[t]);
    orow[t + 128] = __float2bfloat16((v1 - mean) * rstd * gw[t + 128] + bw[t + 128]);
    orow[t + 256] = __float2bfloat16((v2 - mean) * rstd * gw[t + 256] + bw[t + 256]);
}

// ------------------- PTX helpers --------------------------------------------
__device__ __forceinline__ void mma16816(float* c, const uint32_t* a, const uint32_t* b)
{
    asm volatile(
        "mma.sync.aligned.m16n8k16.row.col.f32.bf16.bf16.f32 "
        "{%0,%1,%2,%3}, {%4,%5,%6,%7}, {%8,%9}, {%0,%1,%2,%3};\n"
        : "+f"(c[0]), "+f"(c[1]), "+f"(c[2]), "+f"(c[3])
        : "r"(a[0]), "r"(a[1]), "r"(a[2]), "r"(a[3]), "r"(b[0]), "r"(b[1]));
}

__device__ __forceinline__ void cp_async16(uint32_t dst, const void* src)
{
    asm volatile("cp.async.cg.shared.global [%0], [%1], 16;\n" :: "r"(dst), "l"(src));
}
__device__ __forceinline__ void cp_commit()
{
    asm volatile("cp.async.commit_group;\n");
}
__device__ __forceinline__ void cp_wait1()
{
    asm volatile("cp.async.wait_group 1;\n" ::: "memory");
}

// ------------------- tensor-core GEMM  C = A @ B^T --------------------------
// A: M x K row-major (lda); B: N x K row-major (ldb). Tile BM x BN, BK = 16,
// 3-stage cp.async pipeline, 256 threads (8 warps).
// MODE 0: qkv scatter (+q scale, v transposed)
// MODE 1: batched scores -> S (b,i,h,j)
// MODE 2: batched AV -> o (b,i,h*48+d)
// MODE 3: bias + exact GELU -> bf16
// MODE 4: bias + residual + layerscale -> fp32
template<int BM, int BN, int MODE>
__global__ void __launch_bounds__(256)
gemm_kernel(const bf16* __restrict__ A, const bf16* __restrict__ Bw,
            int M, int N, int K, int lda, int ldb,
            const float* __restrict__ bias, const float* __restrict__ resid,
            const float* __restrict__ gamma, float* __restrict__ fout,
            bf16* __restrict__ bout, bf16* __restrict__ qo,
            bf16* __restrict__ ko, bf16* __restrict__ vo)
{
    constexpr int WM_CNT = BM / 32;                 // warps along M (4 or 2)
    constexpr int WN_TILE = BN * WM_CNT / 8;        // warp tile width along N
    constexpr int NT = WN_TILE / 8;                 // n-fragments per warp
    constexpr int A_STAGE = BM * 24;                // bf16 elements per A stage
    constexpr int B_STAGE = BN * 24;

    __shared__ bf16 As[3][BM][24];
    __shared__ bf16 Bs[3][BN][24];

    const int tid = threadIdx.x;
    const int w = tid >> 5;
    const int l = tid & 31;
    const int g = l >> 2;
    const int t = l & 3;
    const int wm = (w % WM_CNT) * 32;
    const int wn = (w / WM_CNT) * WN_TILE;
    const int m0 = blockIdx.y * BM;
    const int n0 = blockIdx.x * BN;
    const int z  = blockIdx.z;
    const int zb = z >> 3;
    const int zh = z & 7;

    const bf16* Ap = A;
    const bf16* Bp = Bw;
    if (MODE == 1) {
        Ap += (size_t)z * N_ * HD_;
        Bp += (size_t)z * N_ * HD_;
    }
    if (MODE == 2) {
        Ap += (size_t)zb * 8388608 + (size_t)zh * 1024;
        Bp += (size_t)z * 64 * 1024;
    }

    const int arow = tid >> 1;                      // 0..127
    const int acg  = (tid & 1) * 8;
    const int brow = tid >> 1;
    const int bcg  = (tid & 1) * 8;
    const bool doA = (tid < BM * 2);
    const bool doB = (tid < BN * 2);

    const bf16* aSrc = Ap + (size_t)(m0 + (doA ? arow : 0)) * lda + acg;
    const bf16* bSrc = Bp + (size_t)(n0 + (doB ? brow : 0)) * ldb + bcg;
    const uint32_t aDst0 = (uint32_t)__cvta_generic_to_shared(&As[0][doA ? arow : 0][acg]);
    const uint32_t bDst0 = (uint32_t)__cvta_generic_to_shared(&Bs[0][doB ? brow : 0][bcg]);

    float acc[2][NT][4];
    for (int mi = 0; mi < 2; mi++)
        for (int ni = 0; ni < NT; ni++)
            for (int e = 0; e < 4; e++)
                acc[mi][ni][e] = 0.0f;

    const int niter = K >> 4;

    // prologue: stages 0 and 1
    if (doA) cp_async16(aDst0, aSrc);
    if (doB) cp_async16(bDst0, bSrc);
    cp_commit();
    if (niter > 1) {
        if (doA) cp_async16(aDst0 + A_STAGE * 2, aSrc + 16);
        if (doB) cp_async16(bDst0 + B_STAGE * 2, bSrc + 16);
    }
    cp_commit();

    int buf = 0;
    for (int it = 0; it < niter; it++) {
        cp_wait1();                 // stage `it` complete; `it+1` may be in flight
        __syncthreads();
        {
            int pf = buf + 2; if (pf >= 3) pf -= 3;
            if (it + 2 < niter) {
                int kn = (it + 2) << 4;
                if (doA) cp_async16(aDst0 + (uint32_t)pf * (A_STAGE * 2), aSrc + kn);
                if (doB) cp_async16(bDst0 + (uint32_t)pf * (B_STAGE * 2), bSrc + kn);
            }
            cp_commit();            // always: keep group accounting uniform
        }

        const bf16 (*Ab)[24] = As[buf];
        const bf16 (*Bb)[24] = Bs[buf];

        uint32_t af[2][4];
        for (int mi = 0; mi < 2; mi++) {
            int r = wm + mi * 16 + g;
            af[mi][0] = *reinterpret_cast<const uint32_t*>(&Ab[r][2 * t]);
            af[mi][1] = *reinterpret_cast<const uint32_t*>(&Ab[r + 8][2 * t]);
            af[mi][2] = *reinterpret_cast<const uint32_t*>(&Ab[r][2 * t + 8]);
            af[mi][3] = *reinterpret_cast<const uint32_t*>(&Ab[r + 8][2 * t + 8]);
        }
        uint32_t bfm[NT][2];
        for (int ni = 0; ni < NT; ni++) {
            int c = wn + ni * 8 + g;
            bfm[ni][0] = *reinterpret_cast<const uint32_t*>(&Bb[c][2 * t]);
            bfm[ni][1] = *reinterpret_cast<const uint32_t*>(&Bb[c][2 * t + 8]);
        }
        for (int mi = 0; mi < 2; mi++)
            for (int ni = 0; ni < NT; ni++)
                mma16816(acc[mi][ni], af[mi], bfm[ni]);

        buf++; if (buf == 3) buf = 0;
    }

    // ------------------------------ epilogue --------------------------------
    for (int mi = 0; mi < 2; mi++) {
        for (int ni = 0; ni < NT; ni++) {
            for (int hh = 0; hh < 2; hh++) {
                int row = m0 + wm + mi * 16 + g + hh * 8;
                int col = n0 + wn + ni * 8 + 2 * t;
                float v0 = acc[mi][ni][hh * 2 + 0];
                float v1 = acc[mi][ni][hh * 2 + 1];
                if (MODE == 0) {
                    int t3 = col / D_;
                    int r  = col - t3 * D_;
                    int hd = r / HD_;
                    int dd = r - hd * HD_;
                    int bb = row >> 10;
                    int ii = row & 1023;
                    size_t qk = ((size_t)(bb * H_ + hd) * N_ + ii) * HD_ + dd;
                    if (t3 == 0) {
                        __nv_bfloat162 p = __floats2bfloat162_rn(v0 * QSCALE, v1 * QSCALE);
                        *reinterpret_cast<__nv_bfloat162*>(&qo[qk]) = p;
                    } else if (t3 == 1) {
                        __nv_bfloat162 p = __floats2bfloat162_rn(v0, v1);
                        *reinterpret_cast<__nv_bfloat162*>(&ko[qk]) = p;
                    } else {
                        size_t vb = ((size_t)(bb * H_ + hd) * 64 + dd) * N_ + ii;
                        vo[vb]      = __float2bfloat16(v0);
                        vo[vb + N_] = __float2bfloat16(v1);
                    }
                } else if (MODE == 1) {
                    size_t idx = ((size_t)(zb * N_ + row) * H_ + zh) * N_ + col;
                    __nv_bfloat162 p = __floats2bfloat162_rn(v0, v1);
                    *reinterpret_cast<__nv_bfloat162*>(&bout[idx]) = p;
                } else if (MODE == 2) {
                    if (col < HD_) {
                        size_t idx = (size_t)(zb * N_ + row) * D_ + zh * HD_ + col;
                        __nv_bfloat162 p = __floats2bfloat162_rn(v0, v1);
                        *reinterpret_cast<__nv_bfloat162*>(&bout[idx]) = p;
                    }
                } else if (MODE == 3) {
                    float a0 = v0 + bias[col];
                    float a1 = v1 + bias[col + 1];
                    a0 = 0.5f * a0 * (1.0f + erff(a0 * 0.7071067811865475f));
                    a1 = 0.5f * a1 * (1.0f + erff(a1 * 0.7071067811865475f));
                    __nv_bfloat162 p = __floats2bfloat162_rn(a0, a1);
                    *reinterpret_cast<__nv_bfloat162*>(&bout[(size_t)row * N + col]) = p;
                } else {
                    float2 rr = *reinterpret_cast<const float2*>(&resid[(size_t)row * N + col]);
                    float2 o2;
                    o2.x = rr.x + gamma[col]     * (v0 + bias[col]);
                    o2.y = rr.y + gamma[col + 1] * (v1 + bias[col + 1]);
                    *reinterpret_cast<float2*>(&fout[(size_t)row * N + col]) = o2;
                }
            }
        }
    }
}

// ------------------- fused premix + softmax + postmix (in place) ------------
__global__ void __launch_bounds__(256)
softmax_kernel(bf16* __restrict__ S, const float* __restrict__ wl,
               const float* __restrict__ bl, const float* __restrict__ ww,
               const float* __restrict__ bw)
{
    __shared__ bf16  sp[8][1024];
    __shared__ float wls[64];
    __shared__ float bls[8];
    __shared__ float wws[64];
    __shared__ float bws[8];
    const int tid = threadIdx.x;
    if (tid < 64) { wls[tid] = wl[tid]; wws[tid] = ww[tid]; }
    if (tid < 8)  { bls[tid] = bl[tid]; bws[tid] = bw[tid]; }
    const int b = blockIdx.x >> 10;
    const int i = blockIdx.x & 1023;
    uint32_t* gbase = reinterpret_cast<uint32_t*>(S + (size_t)(b * N_ + i) * H_ * N_);
    uint32_t* sbase = reinterpret_cast<uint32_t*>(&sp[0][0]);
    for (int idx = tid; idx < 4096; idx += 256) sbase[idx] = gbase[idx];
    __syncthreads();

    for (int jp = tid; jp < 512; jp += 256) {
        float r0[8];
        float r1[8];
        for (int h = 0; h < 8; h++) {
            __nv_bfloat162 p = *reinterpret_cast<__nv_bfloat162*>(&sp[h][2 * jp]);
            r0[h] = __bfloat162float(p.x);
            r1[h] = __bfloat162float(p.y);
        }
        for (int gg = 0; gg < 8; gg++) {
            float m0 = bls[gg];
            float m1 = bls[gg];
            for (int h = 0; h < 8; h++) {
                m0 += wls[gg * 8 + h] * r0[h];
                m1 += wls[gg * 8 + h] * r1[h];
            }
            *reinterpret_cast<__nv_bfloat162*>(&sp[gg][2 * jp]) = __floats2bfloat162_rn(m0, m1);
        }
    }
    __syncthreads();

    {
        const int gg = tid >> 5;
        const int l  = tid & 31;
        float mx = -1e30f;
        for (int j = l; j < N_; j += 32) mx = fmaxf(mx, __bfloat162float(sp[gg][j]));
        for (int o = 16; o > 0; o >>= 1) mx = fmaxf(mx, __shfl_xor_sync(0xffffffffu, mx, o));
        float sum = 0.0f;
        for (int j = l; j < N_; j += 32) {
            float e = __expf(__bfloat162float(sp[gg][j]) - mx);
            sum += e;
            sp[gg][j] = __float2bfloat16(e);
        }
        for (int o = 16; o > 0; o >>= 1) sum += __shfl_xor_sync(0xffffffffu, sum, o);
        float inv = 1.0f / sum;
        for (int j = l; j < N_; j += 32)
            sp[gg][j] = __float2bfloat16(__bfloat162float(sp[gg][j]) * inv);
    }
    __syncthreads();

    for (int jp = tid; jp < 512; jp += 256) {
        float r0[8];
        float r1[8];
        for (int h = 0; h < 8; h++) {
            __nv_bfloat162 p = *reinterpret_cast<__nv_bfloat162*>(&sp[h][2 * jp]);
            r0[h] = __bfloat162float(p.x);
            r1[h] = __bfloat162float(p.y);
        }
        for (int gg = 0; gg < 8; gg++) {
            float m0 = bws[gg];
            float m1 = bws[gg];
            for (int h = 0; h < 8; h++) {
                m0 += wws[gg * 8 + h] * r0[h];
                m1 += wws[gg * 8 + h] * r1[h];
            }
            reinterpret_cast<__nv_bfloat162*>(gbase)[gg * 512 + jp] =
                __floats2bfloat162_rn(m0, m1);
        }
    }
}

// ------------------- host launcher ------------------------------------------
extern "C" void kernel_launch(void* const* d_in, const int* in_sizes, int n_in,
                              void* d_out, int out_size)
{
    (void)in_sizes; (void)n_in; (void)out_size;
    const float* x      = (const float*)d_in[0];
    const float* ln1_g  = (const float*)d_in[1];
    const float* ln1_b  = (const float*)d_in[2];
    const float* w_qkv  = (const float*)d_in[3];
    const float* w_proj = (const float*)d_in[4];
    const float* b_proj = (const float*)d_in[5];
    const float* w_l    = (const float*)d_in[6];
    const float* b_l    = (const float*)d_in[7];
    const float* w_w    = (const float*)d_in[8];
    const float* b_w    = (const float*)d_in[9];
    const float* ln2_g  = (const float*)d_in[10];
    const float* ln2_b  = (const float*)d_in[11];
    const float* w_fc1  = (const float*)d_in[12];
    const float* b_fc1  = (const float*)d_in[13];
    const float* w_fc2  = (const float*)d_in[14];
    const float* b_fc2  = (const float*)d_in[15];
    const float* gamma1 = (const float*)d_in[16];
    const float* gamma2 = (const float*)d_in[17];
    float* out = (float*)d_out;

    bf16 *hb, *act, *qb, *kb, *vT, *S, *o, *wqkvb, *wprojb, *wfc1b, *wfc2b;
    float* x1;
    cudaGetSymbolAddress((void**)&hb,     g_hb);
    cudaGetSymbolAddress((void**)&act,    g_act);
    cudaGetSymbolAddress((void**)&qb,     g_q);
    cudaGetSymbolAddress((void**)&kb,     g_k);
    cudaGetSymbolAddress((void**)&vT,     g_vT);
    cudaGetSymbolAddress((void**)&S,      g_S);
    cudaGetSymbolAddress((void**)&o,      g_o);
    cudaGetSymbolAddress((void**)&x1,     g_x1);
    cudaGetSymbolAddress((void**)&wqkvb,  g_wqkv);
    cudaGetSymbolAddress((void**)&wprojb, g_wproj);
    cudaGetSymbolAddress((void**)&wfc1b,  g_wfc1);
    cudaGetSymbolAddress((void**)&wfc2b,  g_wfc2);

    // all 4 weight conversions in one launch (442368 float4s)
    cvt_all_kernel<<<1728, 256>>>(w_qkv, wqkvb, w_proj, wprojb,
                                  w_fc1, wfc1b, w_fc2, wfc2b);

    ln_kernel<<<ROWS, 128>>>(x, ln1_g, ln1_b, hb);

    gemm_kernel<128, 128, 0><<<dim3(9, 64, 1), 256>>>(
        hb, wqkvb, ROWS, 1152, 384, 384, 384,
        nullptr, nullptr, nullptr, nullptr, nullptr, qb, kb, vT);

    gemm_kernel<128, 128, 1><<<dim3(8, 8, 64), 256>>>(
        qb, kb, N_, N_, HD_, HD_, HD_,
        nullptr, nullptr, nullptr, nullptr, S, nullptr, nullptr, nullptr);

    softmax_kernel<<<ROWS, 256>>>(S, w_l, b_l, w_w, b_w);

    gemm_kernel<128, 48, 2><<<dim3(1, 8, 64), 256>>>(
        S, vT, N_, 48, N_, 8 * N_, N_,
        nullptr, nullptr, nullptr, nullptr, o, nullptr, nullptr, nullptr);

    gemm_kernel<64, 128, 4><<<dim3(3, 128, 1), 256>>>(
        o, wprojb, ROWS, D_, D_, D_, D_,
        b_proj, x, gamma1, x1, nullptr, nullptr, nullptr, nullptr);

    ln_kernel<<<ROWS, 128>>>(x1, ln2_g, ln2_b, hb);

    gemm_kernel<128, 128, 3><<<dim3(12, 64, 1), 256>>>(
        hb, wfc1b, ROWS, HID_, D_, D_, D_,
        b_fc1, nullptr, nullptr, nullptr, act, nullptr, nullptr, nullptr);

    gemm_kernel<64, 128, 4><<<dim3(3, 128, 1), 256>>>(
        act, wfc2b, ROWS, D_, HID_, HID_, HID_,
        b_fc2, x1, gamma2, out, nullptr, nullptr, nullptr, nullptr);
}

// round 9
// speedup vs baseline: 4.1705x; 1.0083x over previous
#include <cuda_runtime.h>
#include <cuda_bf16.h>
#include <cstdint>
#include <math.h>

typedef __nv_bfloat16 bf16;

#define B_   8
#define N_   1024
#define D_   384
#define H_   8
#define HD_  48
#define HID_ 1536
#define ROWS 8192
#define QSCALE 0.14433756729740643f

// ------------------- static scratch (no allocation allowed) -----------------
__device__ bf16  g_hb  [ROWS * D_];
__device__ bf16  g_act [ROWS * HID_];
__device__ bf16  g_q   [B_ * H_ * N_ * HD_];
__device__ bf16  g_k   [B_ * H_ * N_ * HD_];
__device__ bf16  g_vT  [B_ * H_ * 64 * N_];   // zero-init; pad rows 48..63 never written
__device__ bf16  g_E   [(size_t)B_ * N_ * N_ * H_];   // exp(premixed logits), (b,i,j,h)
__device__ float g_Zp  [B_ * N_ * H_ * 16];           // Z partials per j-block
__device__ bf16  g_o   [ROWS * D_];
__device__ float g_x1  [ROWS * D_];
__device__ bf16  g_wqkv [3 * D_ * D_];
__device__ bf16  g_wproj[D_ * D_];
__device__ bf16  g_wfc1 [HID_ * D_];
__device__ bf16  g_wfc2 [D_ * HID_];

// ------------------- fused fp32 -> bf16 convert for all 4 weights -----------
__global__ void cvt_all_kernel(const float* w0, bf16* o0, const float* w1, bf16* o1,
                               const float* w2, bf16* o2, const float* w3, bf16* o3)
{
    int i = blockIdx.x * 256 + threadIdx.x;            // float4 index
    const float* src;
    bf16* dst;
    int base;
    if (i < 110592)       { src = w0; dst = o0; base = i; }
    else if (i < 147456)  { src = w1; dst = o1; base = i - 110592; }
    else if (i < 294912)  { src = w2; dst = o2; base = i - 147456; }
    else if (i < 442368)  { src = w3; dst = o3; base = i - 294912; }
    else return;
    float4 v = reinterpret_cast<const float4*>(src)[base];
    reinterpret_cast<__nv_bfloat162*>(dst)[2 * base]     = __floats2bfloat162_rn(v.x, v.y);
    reinterpret_cast<__nv_bfloat162*>(dst)[2 * base + 1] = __floats2bfloat162_rn(v.z, v.w);
}

// ------------------- LayerNorm fp32 -> bf16 ---------------------------------
__global__ void ln_kernel(const float* __restrict__ x, const float* __restrict__ gw,
                          const float* __restrict__ bw, bf16* __restrict__ out)
{
    int row = blockIdx.x;
    int t   = threadIdx.x;
    const float* xr = x + (size_t)row * D_;
    float v0 = xr[t], v1 = xr[t + 128], v2 = xr[t + 256];
    float s  = v0 + v1 + v2;
    float ss = v0 * v0 + v1 * v1 + v2 * v2;
    for (int o = 16; o > 0; o >>= 1) {
        s  += __shfl_xor_sync(0xffffffffu, s,  o);
        ss += __shfl_xor_sync(0xffffffffu, ss, o);
    }
    __shared__ float rs[4];
    __shared__ float rq[4];
    if ((t & 31) == 0) { rs[t >> 5] = s; rq[t >> 5] = ss; }
    __syncthreads();
    s  = rs[0] + rs[1] + rs[2] + rs[3];
    ss = rq[0] + rq[1] + rq[2] + rq[3];
    float mean = s * (1.0f / 384.0f);
    float var  = ss * (1.0f / 384.0f) - mean * mean;
    float rstd = rsqrtf(var + 1e-5f);
    bf16* orow = out + (size_t)row * D_;
    orow[t]       = __float2bfloat16((v0 - mean) * rstd * gw[t]       + bw[t]);
    orow[t + 128] = __float2bfloat16((v1 - mean) * rstd * gw[t + 128] + bw[t + 128]);
    orow[t + 256] = __float2bfloat16((v2 - mean) * rstd * gw[t + 256] + bw[t + 256]);
}

// ------------------- PTX helpers --------------------------------------------
__device__ __forceinline__ void mma16816(float* c, const uint32_t* a, const uint32_t* b)
{
    asm volatile(
        "mma.sync.aligned.m16n8k16.row.col.f32.bf16.bf16.f32 "
        "{%0,%1,%2,%3}, {%4,%5,%6,%7}, {%8,%9}, {%0,%1,%2,%3};\n"
        : "+f"(c[0]), "+f"(c[1]), "+f"(c[2]), "+f"(c[3])
        : "r"(a[0]), "r"(a[1]), "r"(a[2]), "r"(a[3]), "r"(b[0]), "r"(b[1]));
}

__device__ __forceinline__ void cp_async16(uint32_t dst, const void* src)
{
    asm volatile("cp.async.cg.shared.global [%0], [%1], 16;\n" :: "r"(dst), "l"(src));
}
__device__ __forceinline__ void cp_commit()
{
    asm volatile("cp.async.commit_group;\n");
}
__device__ __forceinline__ void cp_wait0()
{
    asm volatile("cp.async.wait_group 0;\n" ::: "memory");
}
__device__ __forceinline__ void cp_wait1()
{
    asm volatile("cp.async.wait_group 1;\n" ::: "memory");
}

__device__ __forceinline__ void unpack8(const uint4& v, float* s)
{
    const __nv_bfloat162* p = reinterpret_cast<const __nv_bfloat162*>(&v);
    s[0] = __bfloat162float(p[0].x); s[1] = __bfloat162float(p[0].y);
    s[2] = __bfloat162float(p[1].x); s[3] = __bfloat162float(p[1].y);
    s[4] = __bfloat162float(p[2].x); s[5] = __bfloat162float(p[2].y);
    s[6] = __bfloat162float(p[3].x); s[7] = __bfloat162float(p[3].y);
}

__device__ __forceinline__ uint4 pack8(const float* s)
{
    uint4 v;
    __nv_bfloat162* p = reinterpret_cast<__nv_bfloat162*>(&v);
    p[0] = __floats2bfloat162_rn(s[0], s[1]);
    p[1] = __floats2bfloat162_rn(s[2], s[3]);
    p[2] = __floats2bfloat162_rn(s[4], s[5]);
    p[3] = __floats2bfloat162_rn(s[6], s[7]);
    return v;
}

// ------------------- tensor-core GEMM  C = A @ B^T --------------------------
// 3-stage cp.async pipeline, 256 threads. MODE 0: qkv scatter; MODE 3: GELU;
// MODE 4: bias + residual + layerscale.
template<int BM, int BN, int MODE>
__global__ void __launch_bounds__(256)
gemm_kernel(const bf16* __restrict__ A, const bf16* __restrict__ Bw,
            int M, int N, int K, int lda, int ldb,
            const float* __restrict__ bias, const float* __restrict__ resid,
            const float* __restrict__ gamma, float* __restrict__ fout,
            bf16* __restrict__ bout, bf16* __restrict__ qo,
            bf16* __restrict__ ko, bf16* __restrict__ vo)
{
    constexpr int WM_CNT = BM / 32;
    constexpr int WN_TILE = BN * WM_CNT / 8;
    constexpr int NT = WN_TILE / 8;
    constexpr int A_STAGE = BM * 24;
    constexpr int B_STAGE = BN * 24;

    __shared__ bf16 As[3][BM][24];
    __shared__ bf16 Bs[3][BN][24];

    const int tid = threadIdx.x;
    const int w = tid >> 5;
    const int l = tid & 31;
    const int g = l >> 2;
    const int t = l & 3;
    const int wm = (w % WM_CNT) * 32;
    const int wn = (w / WM_CNT) * WN_TILE;
    const int m0 = blockIdx.y * BM;
    const int n0 = blockIdx.x * BN;

    const bf16* Ap = A;
    const bf16* Bp = Bw;

    const int arow = tid >> 1;
    const int acg  = (tid & 1) * 8;
    const int brow = tid >> 1;
    const int bcg  = (tid & 1) * 8;
    const bool doA = (tid < BM * 2);
    const bool doB = (tid < BN * 2);

    const bf16* aSrc = Ap + (size_t)(m0 + (doA ? arow : 0)) * lda + acg;
    const bf16* bSrc = Bp + (size_t)(n0 + (doB ? brow : 0)) * ldb + bcg;
    const uint32_t aDst0 = (uint32_t)__cvta_generic_to_shared(&As[0][doA ? arow : 0][acg]);
    const uint32_t bDst0 = (uint32_t)__cvta_generic_to_shared(&Bs[0][doB ? brow : 0][bcg]);

    float acc[2][NT][4];
    for (int mi = 0; mi < 2; mi++)
        for (int ni = 0; ni < NT; ni++)
            for (int e = 0; e < 4; e++)
                acc[mi][ni][e] = 0.0f;

    const int niter = K >> 4;

    if (doA) cp_async16(aDst0, aSrc);
    if (doB) cp_async16(bDst0, bSrc);
    cp_commit();
    if (niter > 1) {
        if (doA) cp_async16(aDst0 + A_STAGE * 2, aSrc + 16);
        if (doB) cp_async16(bDst0 + B_STAGE * 2, bSrc + 16);
    }
    cp_commit();

    int buf = 0;
    for (int it = 0; it < niter; it++) {
        cp_wait1();
        __syncthreads();
        {
            int pf = buf + 2; if (pf >= 3) pf -= 3;
            if (it + 2 < niter) {
                int kn = (it + 2) << 4;
                if (doA) cp_async16(aDst0 + (uint32_t)pf * (A_STAGE * 2), aSrc + kn);
                if (doB) cp_async16(bDst0 + (uint32_t)pf * (B_STAGE * 2), bSrc + kn);
            }
            cp_commit();
        }

        const bf16 (*Ab)[24] = As[buf];
        const bf16 (*Bb)[24] = Bs[buf];

        uint32_t af[2][4];
        for (int mi = 0; mi < 2; mi++) {
            int r = wm + mi * 16 + g;
            af[mi][0] = *reinterpret_cast<const uint32_t*>(&Ab[r][2 * t]);
            af[mi][1] = *reinterpret_cast<const uint32_t*>(&Ab[r + 8][2 * t]);
            af[mi][2] = *reinterpret_cast<const uint32_t*>(&Ab[r][2 * t + 8]);
            af[mi][3] = *reinterpret_cast<const uint32_t*>(&Ab[r + 8][2 * t + 8]);
        }
        uint32_t bfm[NT][2];
        for (int ni = 0; ni < NT; ni++) {
            int c = wn + ni * 8 + g;
            bfm[ni][0] = *reinterpret_cast<const uint32_t*>(&Bb[c][2 * t]);
            bfm[ni][1] = *reinterpret_cast<const uint32_t*>(&Bb[c][2 * t + 8]);
        }
        for (int mi = 0; mi < 2; mi++)
            for (int ni = 0; ni < NT; ni++)
                mma16816(acc[mi][ni], af[mi], bfm[ni]);

        buf++; if (buf == 3) buf = 0;
    }

    for (int mi = 0; mi < 2; mi++) {
        for (int ni = 0; ni < NT; ni++) {
            for (int hh = 0; hh < 2; hh++) {
                int row = m0 + wm + mi * 16 + g + hh * 8;
                int col = n0 + wn + ni * 8 + 2 * t;
                float v0 = acc[mi][ni][hh * 2 + 0];
                float v1 = acc[mi][ni][hh * 2 + 1];
                if (MODE == 0) {
                    int t3 = col / D_;
                    int r  = col - t3 * D_;
                    int hd = r / HD_;
                    int dd = r - hd * HD_;
                    int bb = row >> 10;
                    int ii = row & 1023;
                    size_t qk = ((size_t)(bb * H_ + hd) * N_ + ii) * HD_ + dd;
                    if (t3 == 0) {
                        __nv_bfloat162 p = __floats2bfloat162_rn(v0 * QSCALE, v1 * QSCALE);
                        *reinterpret_cast<__nv_bfloat162*>(&qo[qk]) = p;
                    } else if (t3 == 1) {
                        __nv_bfloat162 p = __floats2bfloat162_rn(v0, v1);
                        *reinterpret_cast<__nv_bfloat162*>(&ko[qk]) = p;
                    } else {
                        size_t vb = ((size_t)(bb * H_ + hd) * 64 + dd) * N_ + ii;
                        vo[vb]      = __float2bfloat16(v0);
                        vo[vb + N_] = __float2bfloat16(v1);
                    }
                } else if (MODE == 3) {
                    float a0 = v0 + bias[col];
                    float a1 = v1 + bias[col + 1];
                    a0 = 0.5f * a0 * (1.0f + erff(a0 * 0.7071067811865475f));
                    a1 = 0.5f * a1 * (1.0f + erff(a1 * 0.7071067811865475f));
                    __nv_bfloat162 p = __floats2bfloat162_rn(a0, a1);
                    *reinterpret_cast<__nv_bfloat162*>(&bout[(size_t)row * N + col]) = p;
                } else {
                    float2 rr = *reinterpret_cast<const float2*>(&resid[(size_t)row * N + col]);
                    float2 o2;
                    o2.x = rr.x + gamma[col]     * (v0 + bias[col]);
                    o2.y = rr.y + gamma[col + 1] * (v1 + bias[col + 1]);
                    *reinterpret_cast<float2*>(&fout[(size_t)row * N + col]) = o2;
                }
            }
        }
    }
}

// ------------------- K1: QK^T (8 heads) + premix + exp + Z partials ---------
// grid (16 j-blocks, 16 i-blocks, 8 b); 256 threads; dynamic smem 95520 B.
__global__ void __launch_bounds__(256)
score_mix_kernel(const bf16* __restrict__ q, const bf16* __restrict__ k,
                 const float* __restrict__ wl, const float* __restrict__ bl,
                 bf16* __restrict__ E, float* __restrict__ Zp)
{
    extern __shared__ char sm1[];
    bf16*  Qs  = reinterpret_cast<bf16*>(sm1);            // [2][64][56]
    bf16*  Ks  = reinterpret_cast<bf16*>(sm1 + 14336);    // [2][64][56]
    bf16*  Es  = reinterpret_cast<bf16*>(sm1 + 28672);    // [64][520]  (row 1040 B)
    float* wls = reinterpret_cast<float*>(sm1 + 95232);   // 64
    float* bls = reinterpret_cast<float*>(sm1 + 95488);   // 8

    const int tid = threadIdx.x;
    const int jb  = blockIdx.x;
    const int j0  = jb * 64;
    const int i0  = blockIdx.y * 64;
    const int b   = blockIdx.z;

    if (tid < 64) wls[tid] = wl[tid];
    if (tid < 8)  bls[tid] = bl[tid];

    const int w = tid >> 5, l = tid & 31, gq = l >> 2, t = l & 3;
    const int wm = (w & 3) * 16;          // M 64: 4 warp rows
    const int wn = (w >> 2) * 32;         // N 64: 2 warp cols of 32

    // h-tile loader (Q and K tiles, 64x48 each) into buffer `buf`
    auto loadQK = [&](int h, int buf) {
        const bf16* qsrc = q + ((size_t)(b * H_ + h) * N_ + i0) * HD_;
        const bf16* ksrc = k + ((size_t)(b * H_ + h) * N_ + j0) * HD_;
        for (int idx = tid; idx < 384; idx += 256) {
            int r = idx / 6;
            int c = (idx - r * 6) * 8;
            cp_async16((uint32_t)__cvta_generic_to_shared(Qs + buf * 3584 + r * 56 + c),
                       qsrc + (size_t)r * HD_ + c);
            cp_async16((uint32_t)__cvta_generic_to_shared(Ks + buf * 3584 + r * 56 + c),
                       ksrc + (size_t)r * HD_ + c);
        }
    };

    loadQK(0, 0);
    cp_commit();

    for (int h = 0; h < 8; h++) {
        cp_wait0();
        __syncthreads();
        if (h + 1 < 8) loadQK(h + 1, (h + 1) & 1);
        cp_commit();

        const bf16* Qb = Qs + (h & 1) * 3584;
        const bf16* Kb = Ks + (h & 1) * 3584;

        float acc[4][4];
        for (int nf = 0; nf < 4; nf++)
            for (int e = 0; e < 4; e++) acc[nf][e] = 0.0f;

        for (int k0 = 0; k0 < 48; k0 += 16) {
            uint32_t a[4];
            a[0] = *reinterpret_cast<const uint32_t*>(Qb + (wm + gq) * 56 + k0 + 2 * t);
            a[1] = *reinterpret_cast<const uint32_t*>(Qb + (wm + gq + 8) * 56 + k0 + 2 * t);
            a[2] = *reinterpret_cast<const uint32_t*>(Qb + (wm + gq) * 56 + k0 + 2 * t + 8);
            a[3] = *reinterpret_cast<const uint32_t*>(Qb + (wm + gq + 8) * 56 + k0 + 2 * t + 8);
            for (int nf = 0; nf < 4; nf++) {
                uint32_t bb[2];
                bb[0] = *reinterpret_cast<const uint32_t*>(Kb + (wn + nf * 8 + gq) * 56 + k0 + 2 * t);
                bb[1] = *reinterpret_cast<const uint32_t*>(Kb + (wn + nf * 8 + gq) * 56 + k0 + 2 * t + 8);
                mma16816(acc[nf], a, bb);
            }
        }
        // stage raw scores for this head into Es [i][j][h]
        for (int nf = 0; nf < 4; nf++) {
            for (int hh = 0; hh < 2; hh++) {
                int row = wm + gq + hh * 8;
                int col = wn + nf * 8 + 2 * t;
                Es[row * 520 + col * 8 + h]       = __float2bfloat16(acc[nf][hh * 2 + 0]);
                Es[row * 520 + (col + 1) * 8 + h] = __float2bfloat16(acc[nf][hh * 2 + 1]);
            }
        }
    }
    __syncthreads();

    // mix + exp + E store + Z partials. thread: row mi, j = mj0 + 4p
    const int mi  = tid >> 2;
    const int mj0 = tid & 3;
    float zacc[8];
    for (int gg = 0; gg < 8; gg++) zacc[gg] = 0.0f;

    uint4* Eg = reinterpret_cast<uint4*>(E);
    for (int p = 0; p < 16; p++) {
        int j = mj0 + p * 4;
        uint4 sv = *reinterpret_cast<const uint4*>(Es + mi * 520 + j * 8);
        float s[8];
        unpack8(sv, s);
        float e[8];
        for (int gg = 0; gg < 8; gg++) {
            float m = bls[gg];
            for (int hh = 0; hh < 8; hh++) m += wls[gg * 8 + hh] * s[hh];
            float ev = __expf(m);
            e[gg] = ev;
            zacc[gg] += ev;
        }
        Eg[(size_t)(b * N_ + i0 + mi) * N_ + j0 + j] = pack8(e);
    }
    // reduce z over the 4 threads sharing a row (lanes l^1, l^2)
    for (int gg = 0; gg < 8; gg++) {
        zacc[gg] += __shfl_xor_sync(0xffffffffu, zacc[gg], 1);
        zacc[gg] += __shfl_xor_sync(0xffffffffu, zacc[gg], 2);
    }
    if ((tid & 3) == 0) {
        float* zp = Zp + (size_t)(b * N_ + i0 + mi) * 128 + jb;
        for (int gg = 0; gg < 8; gg++) zp[gg * 16] = zacc[gg];
    }
}

// ------------------- K2: normalize + postmix + AV ---------------------------
// grid (32 i-blocks, 8 b); 256 threads; dynamic smem 111904 B.
__global__ void __launch_bounds__(256)
attn_pv_kernel(const bf16* __restrict__ E, const float* __restrict__ Zp,
               const bf16* __restrict__ vT, const float* __restrict__ ww,
               const float* __restrict__ bw, bf16* __restrict__ o)
{
    extern __shared__ char sm2[];
    bf16*  Vs   = reinterpret_cast<bf16*>(sm2);             // [8][64][72]
    bf16*  Pb   = reinterpret_cast<bf16*>(sm2 + 73728);     // [8][32][72]
    float* invZ = reinterpret_cast<float*>(sm2 + 110592);   // [32][8]
    float* wws  = reinterpret_cast<float*>(sm2 + 111616);   // 64
    float* bws  = reinterpret_cast<float*>(sm2 + 111872);   // 8

    const int tid = threadIdx.x;
    const int i0  = blockIdx.x * 32;
    const int b   = blockIdx.y;
    const int w = tid >> 5, l = tid & 31, gq = l >> 2, t = l & 3;
    const int wm = (w & 1) * 16;          // M 32
    const int wn = (w >> 1) * 16;         // N 64 padded (warps with wn=48 idle in mma)

    if (tid < 64) wws[tid] = ww[tid];
    if (tid < 8)  bws[tid] = bw[tid];
    {
        int i = tid >> 3, gg = tid & 7;
        const float* zp = Zp + (size_t)(b * N_ + i0 + i) * 128 + gg * 16;
        float s = 0.0f;
        for (int qq = 0; qq < 16; qq++) s += zp[qq];
        invZ[i * 8 + gg] = 1.0f / s;
    }
    __syncthreads();

    float acc[8][2][4];
    for (int gg = 0; gg < 8; gg++)
        for (int nf = 0; nf < 2; nf++)
            for (int e = 0; e < 4; e++) acc[gg][nf][e] = 0.0f;

    const int ei  = tid >> 3;     // row 0..31
    const int ej0 = tid & 7;
    const uint4* Eg = reinterpret_cast<const uint4*>(E);

    float izr[8];
    for (int hh = 0; hh < 8; hh++) izr[hh] = invZ[ei * 8 + hh];

    for (int jblk = 0; jblk < 16; jblk++) {
        const int j0 = jblk * 64;
        // E loads to registers (8 positions, uint4 each)
        uint4 ev[8];
        for (int p = 0; p < 8; p++) {
            int j = ej0 + p * 8;
            ev[p] = Eg[(size_t)(b * N_ + i0 + ei) * N_ + j0 + j];
        }
        __syncthreads();    // previous mma done; smem reusable
        // V tiles: 8 g x 64 d-rows x 64 j
        for (int idx = tid; idx < 4096; idx += 256) {
            int gg = idx >> 9;
            int r  = (idx >> 3) & 63;
            int c  = (idx & 7) * 8;
            *reinterpret_cast<uint4*>(Vs + (gg * 64 + r) * 72 + c) =
                *reinterpret_cast<const uint4*>(vT + ((size_t)(b * H_ + gg) * 64 + r) * N_ + j0 + c);
        }
        // normalize + postmix -> Pb
        for (int p = 0; p < 8; p++) {
            int j = ej0 + p * 8;
            float s[8];
            unpack8(ev[p], s);
            float ph[8];
            for (int hh = 0; hh < 8; hh++) ph[hh] = s[hh] * izr[hh];
            for (int gg = 0; gg < 8; gg++) {
                float pv = bws[gg];
                for (int hh = 0; hh < 8; hh++) pv += wws[gg * 8 + hh] * ph[hh];
                Pb[(gg * 32 + ei) * 72 + j] = __float2bfloat16(pv);
            }
        }
        __syncthreads();
        // AV mma per output head
        if (wn < 48) {
            for (int gg = 0; gg < 8; gg++) {
                const bf16* Pg = Pb + gg * 32 * 72;
                const bf16* Vg = Vs + gg * 64 * 72;
                for (int k0 = 0; k0 < 64; k0 += 16) {
                    uint32_t a[4];
                    a[0] = *reinterpret_cast<const uint32_t*>(Pg + (wm + gq) * 72 + k0 + 2 * t);
                    a[1] = *reinterpret_cast<const uint32_t*>(Pg + (wm + gq + 8) * 72 + k0 + 2 * t);
                    a[2] = *reinterpret_cast<const uint32_t*>(Pg + (wm + gq) * 72 + k0 + 2 * t + 8);
                    a[3] = *reinterpret_cast<const uint32_t*>(Pg + (wm + gq + 8) * 72 + k0 + 2 * t + 8);
                    for (int nf = 0; nf < 2; nf++) {
                        uint32_t bb[2];
                        bb[0] = *reinterpret_cast<const uint32_t*>(Vg + (wn + nf * 8 + gq) * 72 + k0 + 2 * t);
                        bb[1] = *reinterpret_cast<const uint32_t*>(Vg + (wn + nf * 8 + gq) * 72 + k0 + 2 * t + 8);
                        mma16816(acc[gg][nf], a, bb);
                    }
                }
            }
        }
    }

    // epilogue: O[g][i][d] -> o (b, i, g*48+d)
    if (wn < 48) {
        for (int gg = 0; gg < 8; gg++) {
            for (int nf = 0; nf < 2; nf++) {
                for (int hh = 0; hh < 2; hh++) {
                    int row = wm + gq + hh * 8;
                    int col = wn + nf * 8 + 2 * t;
                    if (col < HD_) {
                        __nv_bfloat162 p = __floats2bfloat162_rn(acc[gg][nf][hh * 2 + 0],
                                                                 acc[gg][nf][hh * 2 + 1]);
                        *reinterpret_cast<__nv_bfloat162*>(
                            &o[(size_t)(b * N_ + i0 + row) * D_ + gg * HD_ + col]) = p;
                    }
                }
            }
        }
    }
}

// ------------------- host launcher ------------------------------------------
extern "C" void kernel_launch(void* const* d_in, const int* in_sizes, int n_in,
                              void* d_out, int out_size)
{
    (void)in_sizes; (void)n_in; (void)out_size;
    const float* x      = (const float*)d_in[0];
    const float* ln1_g  = (const float*)d_in[1];
    const float* ln1_b  = (const float*)d_in[2];
    const float* w_qkv  = (const float*)d_in[3];
    const float* w_proj = (const float*)d_in[4];
    const float* b_proj = (const float*)d_in[5];
    const float* w_l    = (const float*)d_in[6];
    const float* b_l    = (const float*)d_in[7];
    const float* w_w    = (const float*)d_in[8];
    const float* b_w    = (const float*)d_in[9];
    const float* ln2_g  = (const float*)d_in[10];
    const float* ln2_b  = (const float*)d_in[11];
    const float* w_fc1  = (const float*)d_in[12];
    const float* b_fc1  = (const float*)d_in[13];
    const float* w_fc2  = (const float*)d_in[14];
    const float* b_fc2  = (const float*)d_in[15];
    const float* gamma1 = (const float*)d_in[16];
    const float* gamma2 = (const float*)d_in[17];
    float* out = (float*)d_out;

    bf16 *hb, *act, *qb, *kb, *vT, *E, *o, *wqkvb, *wprojb, *wfc1b, *wfc2b;
    float *x1, *Zp;
    cudaGetSymbolAddress((void**)&hb,     g_hb);
    cudaGetSymbolAddress((void**)&act,    g_act);
    cudaGetSymbolAddress((void**)&qb,     g_q);
    cudaGetSymbolAddress((void**)&kb,     g_k);
    cudaGetSymbolAddress((void**)&vT,     g_vT);
    cudaGetSymbolAddress((void**)&E,      g_E);
    cudaGetSymbolAddress((void**)&Zp,     g_Zp);
    cudaGetSymbolAddress((void**)&o,      g_o);
    cudaGetSymbolAddress((void**)&x1,     g_x1);
    cudaGetSymbolAddress((void**)&wqkvb,  g_wqkv);
    cudaGetSymbolAddress((void**)&wprojb, g_wproj);
    cudaGetSymbolAddress((void**)&wfc1b,  g_wfc1);
    cudaGetSymbolAddress((void**)&wfc2b,  g_wfc2);

    cudaFuncSetAttribute(score_mix_kernel, cudaFuncAttributeMaxDynamicSharedMemorySize, 95520);
    cudaFuncSetAttribute(attn_pv_kernel,   cudaFuncAttributeMaxDynamicSharedMemorySize, 111904);

    cvt_all_kernel<<<1728, 256>>>(w_qkv, wqkvb, w_proj, wprojb,
                                  w_fc1, wfc1b, w_fc2, wfc2b);

    ln_kernel<<<ROWS, 128>>>(x, ln1_g, ln1_b, hb);

    gemm_kernel<128, 128, 0><<<dim3(9, 64, 1), 256>>>(
        hb, wqkvb, ROWS, 1152, 384, 384, 384,
        nullptr, nullptr, nullptr, nullptr, nullptr, qb, kb, vT);

    score_mix_kernel<<<dim3(16, 16, 8), 256, 95520>>>(qb, kb, w_l, b_l, E, Zp);

    attn_pv_kernel<<<dim3(32, 8), 256, 111904>>>(E, Zp, vT, w_w, b_w, o);

    gemm_kernel<64, 128, 4><<<dim3(3, 128, 1), 256>>>(
        o, wprojb, ROWS, D_, D_, D_, D_,
        b_proj, x, gamma1, x1, nullptr, nullptr, nullptr, nullptr);

    ln_kernel<<<ROWS, 128>>>(x1, ln2_g, ln2_b, hb);

    gemm_kernel<128, 128, 3><<<dim3(12, 64, 1), 256>>>(
        hb, wfc1b, ROWS, HID_, D_, D_, D_,
        b_fc1, nullptr, nullptr, nullptr, act, nullptr, nullptr, nullptr);

    gemm_kernel<64, 128, 4><<<dim3(3, 128, 1), 256>>>(
        act, wfc2b, ROWS, D_, HID_, HID_, HID_,
        b_fc2, x1, gamma2, out, nullptr, nullptr, nullptr, nullptr);
}